// round 10
// baseline (speedup 1.0000x reference)
#include <cuda_runtime.h>
#include <cuda_bf16.h>
#include <cstdint>

#define NNODES 50000
#define NEDGES 200000
#define NGRAPH 2048
#define D_IN   64
#define D_H    1000
#define D_ENC  128

typedef __nv_bfloat16 bf16;

// ---------------- scratch (static device allocations; no cudaMalloc) --------
__device__ float g_aggx [NNODES * D_IN];
__device__ float g_aggy [NNODES * D_ENC];
__device__ float g_h2f  [NNODES * D_ENC];
__device__ float g_aggh2[NNODES * D_ENC];
__device__ float g_z2   [NNODES * 256];   // cols 0..127 rel, 128..255 root
__device__ float g_z4   [NNODES * 64];    // z4 rel half only (root fused into out)
__device__ float g_sums [NGRAPH * D_ENC];
__device__ float g_counts[NGRAPH];
__device__ int   g_ei32[2 * NEDGES];
__device__ int   g_batch32[NNODES];

__device__ __align__(16) bf16 g_x_h   [NNODES * D_IN],  g_x_l   [NNODES * D_IN];
__device__ __align__(16) bf16 g_aggx_h[NNODES * D_IN],  g_aggx_l[NNODES * D_IN];
__device__ __align__(16) bf16 g_h1_h  [(size_t)NNODES * D_H], g_h1_l[(size_t)NNODES * D_H];
__device__ __align__(16) bf16 g_h2_h  [NNODES * D_ENC], g_h2_l [NNODES * D_ENC];
__device__ __align__(16) bf16 g_ah2_h [NNODES * D_ENC], g_ah2_l[NNODES * D_ENC];
__device__ __align__(16) bf16 g_w1r_h[D_H * D_IN],  g_w1r_l[D_H * D_IN];
__device__ __align__(16) bf16 g_w1o_h[D_H * D_IN],  g_w1o_l[D_H * D_IN];
__device__ __align__(16) bf16 g_w2_h [256 * D_H],   g_w2_l [256 * D_H];
__device__ __align__(16) bf16 g_w3r_h[D_H * D_ENC], g_w3r_l[D_H * D_ENC];
__device__ __align__(16) bf16 g_w3o_h[D_H * D_ENC], g_w3o_l[D_H * D_ENC];
__device__ __align__(16) bf16 g_w4_h [128 * D_H],   g_w4_l [128 * D_H];

// ---------------- helpers ----------------------------------------------------
__device__ __forceinline__ uint2 split2(float v0, float v1) {
    uint32_t pH;
    asm("cvt.rn.bf16x2.f32 %0, %1, %2;" : "=r"(pH) : "f"(v1), "f"(v0));
    float h0 = __uint_as_float(pH << 16);
    float h1 = __uint_as_float(pH & 0xffff0000u);
    float r0 = v0 - h0, r1 = v1 - h1;
    uint32_t pL;
    asm("cvt.rn.bf16x2.f32 %0, %1, %2;" : "=r"(pL) : "f"(r1), "f"(r0));
    return make_uint2(pH, pL);
}
__device__ __forceinline__ void mma16816(float* d, const uint32_t* a, uint32_t b0, uint32_t b1) {
    asm volatile(
        "mma.sync.aligned.m16n8k16.row.col.f32.bf16.bf16.f32 "
        "{%0,%1,%2,%3}, {%4,%5,%6,%7}, {%8,%9}, {%0,%1,%2,%3};"
        : "+f"(d[0]), "+f"(d[1]), "+f"(d[2]), "+f"(d[3])
        : "r"(a[0]), "r"(a[1]), "r"(a[2]), "r"(a[3]), "r"(b0), "r"(b1));
}
__device__ __forceinline__ uint32_t cvta_s(const void* p) {
    uint32_t a;
    asm("{ .reg .u64 t; cvta.to.shared.u64 t, %1; cvt.u32.u64 %0, t; }" : "=r"(a) : "l"(p));
    return a;
}
#define LDMX4(r, a) \
    asm volatile("ldmatrix.sync.aligned.m8n8.x4.shared.b16 {%0,%1,%2,%3}, [%4];" \
        : "=r"((r)[0]), "=r"((r)[1]), "=r"((r)[2]), "=r"((r)[3]) : "r"(a))

// ---------------- setup kernels ----------------------------------------------
// convert with inline dtype detection (every block recomputes cheap flag)
__global__ void convert_kernel(const int* __restrict__ ei_raw, const int* __restrict__ batch_raw) {
    int odd_zero = 1;
    #pragma unroll
    for (int k = 0; k < 16; ++k)
        if (__ldg(&ei_raw[2 * k + 1]) != 0) odd_zero = 0;
    int i = blockIdx.x * blockDim.x + threadIdx.x;
    if (i < 2 * NEDGES) g_ei32[i] = odd_zero ? ei_raw[2 * i] : ei_raw[i];
    if (i < NNODES)     g_batch32[i] = odd_zero ? batch_raw[2 * i] : batch_raw[i];
}

// merged zero + weight/x split
__global__ void setup_kernel(
    const float* __restrict__ w1r, const float* __restrict__ w1o,
    const float* __restrict__ w2r, const float* __restrict__ w2o,
    const float* __restrict__ w3r, const float* __restrict__ w3o,
    const float* __restrict__ w4r, const float* __restrict__ w4o,
    const float* __restrict__ x) {
    float4 z = make_float4(0.f, 0.f, 0.f, 0.f);
    float4* aggy  = reinterpret_cast<float4*>(g_aggy);
    float4* aggh2 = reinterpret_cast<float4*>(g_aggh2);
    float4* aggx  = reinterpret_cast<float4*>(g_aggx);
    float4* sums  = reinterpret_cast<float4*>(g_sums);
    float4* cnts  = reinterpret_cast<float4*>(g_counts);
    for (int i = blockIdx.x * blockDim.x + threadIdx.x; i < NNODES * D_ENC / 4;
         i += gridDim.x * blockDim.x) {
        aggy[i] = z;
        aggh2[i] = z;
        if (i < NNODES * D_IN / 4) aggx[i] = z;
        if (i < NGRAPH * D_ENC / 4) sums[i] = z;
        if (i < NGRAPH / 4) cnts[i] = z;
    }
    const int H1 = D_H * D_IN / 2;
    const int H2 = 128 * D_H / 2;
    const int H3 = D_H * D_ENC / 2;
    const int H4 = 64 * D_H / 2;
    const int HX = NNODES * D_IN / 2;
    const int TOTP = 2 * H1 + 2 * H2 + 2 * H3 + 2 * H4 + HX;
    for (int p = blockIdx.x * blockDim.x + threadIdx.x; p < TOTP;
         p += gridDim.x * blockDim.x) {
        const float* src; bf16 *dh, *dl; int j = p;
        if (j < H1)              { src = w1r; dh = g_w1r_h; dl = g_w1r_l; }
        else if ((j -= H1) < H1) { src = w1o; dh = g_w1o_h; dl = g_w1o_l; }
        else if ((j -= H1) < H2) { src = w2r; dh = g_w2_h; dl = g_w2_l; }
        else if ((j -= H2) < H2) { src = w2o; dh = g_w2_h + 2 * H2; dl = g_w2_l + 2 * H2; }
        else if ((j -= H2) < H3) { src = w3r; dh = g_w3r_h; dl = g_w3r_l; }
        else if ((j -= H3) < H3) { src = w3o; dh = g_w3o_h; dl = g_w3o_l; }
        else if ((j -= H3) < H4) { src = w4r; dh = g_w4_h; dl = g_w4_l; }
        else if ((j -= H4) < H4) { src = w4o; dh = g_w4_h + 2 * H4; dl = g_w4_l + 2 * H4; }
        else { j -= H4;            src = x;   dh = g_x_h;  dl = g_x_l; }
        int e = j * 2;
        float2 v = *reinterpret_cast<const float2*>(&src[e]);
        uint2 s = split2(v.x, v.y);
        *reinterpret_cast<uint32_t*>(&dh[e]) = s.x;
        *reinterpret_cast<uint32_t*>(&dl[e]) = s.y;
    }
}
__global__ void split_kernel(const float* __restrict__ src, bf16* __restrict__ hi,
                             bf16* __restrict__ lo, int n) {
    for (int e = (blockIdx.x * blockDim.x + threadIdx.x) * 2; e < n;
         e += gridDim.x * blockDim.x * 2) {
        float2 v = *reinterpret_cast<const float2*>(&src[e]);
        uint2 s = split2(v.x, v.y);
        *reinterpret_cast<uint32_t*>(&hi[e]) = s.x;
        *reinterpret_cast<uint32_t*>(&lo[e]) = s.y;
    }
}
// segment-sum over edges: 8 features per thread (2 float4 loads in flight)
template <int F>
__global__ void edge_agg_kernel(const float* __restrict__ feat, int featStride,
                                float* __restrict__ out, int outStride) {
    constexpr int TPE = F / 8;
    int idx = blockIdx.x * blockDim.x + threadIdx.x;
    int e = idx / TPE;
    int f = (idx % TPE) * 8;
    if (e >= NEDGES) return;
    int s = g_ei32[e];
    int d = g_ei32[NEDGES + e];
    const float4* src = reinterpret_cast<const float4*>(&feat[(size_t)s * featStride + f]);
    float4 v0 = src[0];
    float4 v1 = src[1];
    float* o = &out[(size_t)d * outStride + f];
    atomicAdd(o + 0, v0.x); atomicAdd(o + 1, v0.y);
    atomicAdd(o + 2, v0.z); atomicAdd(o + 3, v0.w);
    atomicAdd(o + 4, v1.x); atomicAdd(o + 5, v1.y);
    atomicAdd(o + 6, v1.z); atomicAdd(o + 7, v1.w);
}
// fused: h2 = relu(aggy + z2_root + b2); fp32 + packed hi/lo; pool (4 el/thread)
__global__ void combine_pool_kernel(const float* __restrict__ b2) {
    int idx = blockIdx.x * blockDim.x + threadIdx.x;
    if (idx >= NNODES * 32) return;
    int i = idx >> 5, f = (idx & 31) * 4;
    float4 ag = *reinterpret_cast<const float4*>(&g_aggy[i * D_ENC + f]);
    float4 zr = *reinterpret_cast<const float4*>(&g_z2[(size_t)i * 256 + 128 + f]);
    float4 bb = *reinterpret_cast<const float4*>(&b2[f]);
    float v0 = fmaxf(ag.x + zr.x + bb.x, 0.f);
    float v1 = fmaxf(ag.y + zr.y + bb.y, 0.f);
    float v2 = fmaxf(ag.z + zr.z + bb.z, 0.f);
    float v3 = fmaxf(ag.w + zr.w + bb.w, 0.f);
    *reinterpret_cast<float4*>(&g_h2f[i * D_ENC + f]) = make_float4(v0, v1, v2, v3);
    uint2 s01 = split2(v0, v1);
    uint2 s23 = split2(v2, v3);
    *reinterpret_cast<uint2*>(&g_h2_h[i * D_ENC + f]) = make_uint2(s01.x, s23.x);
    *reinterpret_cast<uint2*>(&g_h2_l[i * D_ENC + f]) = make_uint2(s01.y, s23.y);
    int b = g_batch32[i];
    atomicAdd(&g_sums[b * D_ENC + f + 0], v0);
    atomicAdd(&g_sums[b * D_ENC + f + 1], v1);
    atomicAdd(&g_sums[b * D_ENC + f + 2], v2);
    atomicAdd(&g_sums[b * D_ENC + f + 3], v3);
    if (f == 0) atomicAdd(&g_counts[b], 1.f);
}
__global__ void encoded_kernel(float* __restrict__ enc) {
    int idx = blockIdx.x * blockDim.x + threadIdx.x;
    if (idx >= NGRAPH * D_ENC) return;
    int g = idx >> 7;
    enc[idx] = g_sums[idx] / fmaxf(g_counts[g], 1.f);
}

// ---------------- pipelined mma.sync bf16x3 GEMM (R6/R9 config) --------------
// block 128x128; 8 warps (4m x 2n); warp tile 32x64.
// K-chunk 32, 2-stage cp.async pipeline, ldmatrix.x4 fragment loads, 2 CTA/SM.
#define CHUNK 32
#define SROW  80
#define GTILE (128 * SROW)        // 10240
#define GSTAGE (4 * GTILE)        // 40960

template <bool DUAL_A, bool RELU, bool BIAS, bool BF16OUT, bool OSPLIT>
__global__ void __launch_bounds__(256, 2) mmagemm(
    float* __restrict__ Cf, bf16* __restrict__ Ch, bf16* __restrict__ Cl,
    const bf16* __restrict__ A1h, const bf16* __restrict__ A1l,
    const bf16* __restrict__ A2h, const bf16* __restrict__ A2l,
    const bf16* __restrict__ B1h, const bf16* __restrict__ B1l,
    const bf16* __restrict__ B2h, const bf16* __restrict__ B2l,
    const float* __restrict__ bias, int M, int K, int O,
    float* __restrict__ C2, const float* __restrict__ bias2) {

    extern __shared__ char smraw[];
    const uint32_t smemBase = cvta_s(smraw);

    const int tid = threadIdx.x;
    const int wid = tid >> 5, lane = tid & 31;
    const int g = lane >> 2, t = lane & 3;
    const int warpM = (wid & 3) * 32, warpN = (wid >> 2) * 64;
    const int rowBase = blockIdx.y * 128, colBase = blockIdx.x * 128;

    const int laneRowA = (lane & 7) + ((lane & 8) ? 8 : 0);
    const int aK = (lane & 16) ? 16 : 0;
    const int laneRowW = (lane & 7) + ((lane & 16) ? 8 : 0);
    const int wK = (lane & 8) ? 16 : 0;
    uint32_t aoff[2], woff[4];
    #pragma unroll
    for (int mi = 0; mi < 2; ++mi)
        aoff[mi] = (uint32_t)((warpM + mi * 16 + laneRowA) * SROW + aK);
    #pragma unroll
    for (int p = 0; p < 4; ++p)
        woff[p] = (uint32_t)((warpN + p * 16 + laneRowW) * SROW + wK);

    float acc[2][8][4];
    #pragma unroll
    for (int a = 0; a < 2; ++a)
        #pragma unroll
        for (int b = 0; b < 8; ++b)
            #pragma unroll
            for (int c = 0; c < 4; ++c) acc[a][b][c] = 0.f;

    const int KC = (K + CHUNK - 1) / CHUNK;
    const int C = (DUAL_A ? 2 : 1) * KC;

    auto loadChunk = [&](int i, int stage) {
        int sIdx = DUAL_A ? (i / KC) : 0;
        int c = i - sIdx * KC;
        int k0 = c * CHUNK;
        const bf16* Ah = (DUAL_A && sIdx) ? A2h : A1h;
        const bf16* Al = (DUAL_A && sIdx) ? A2l : A1l;
        const bf16* Wh = (DUAL_A && sIdx) ? B2h : B1h;
        const bf16* Wl = (DUAL_A && sIdx) ? B2l : B1l;
        uint32_t sb = smemBase + stage * GSTAGE;
        #pragma unroll
        for (int j = 0; j < 8; ++j) {
            int idx = tid + j * 256;
            int tile = idx >> 9;
            int r = (idx >> 2) & 127;
            int sg = idx & 3;
            int gk = k0 + sg * 8;
            const bf16* src;
            int ok;
            if (tile < 2) {
                int gr = rowBase + r;
                ok = (gr < M) && (gk + 8 <= K);
                const bf16* base = tile ? Al : Ah;
                src = ok ? base + (size_t)gr * K + gk : base;
            } else {
                int gw = colBase + r;
                ok = (gw < O) && (gk + 8 <= K);
                const bf16* base = (tile == 2) ? Wh : Wl;
                src = ok ? base + (size_t)gw * K + gk : base;
            }
            uint32_t dst = sb + tile * GTILE + (uint32_t)(r * SROW + sg * 16);
            int sz = ok ? 16 : 0;
            asm volatile("cp.async.cg.shared.global [%0], [%1], 16, %2;"
                         :: "r"(dst), "l"(src), "r"(sz) : "memory");
        }
        asm volatile("cp.async.commit_group;" ::: "memory");
    };

    auto computeChunk = [&](int stage) {
        uint32_t sb = smemBase + stage * GSTAGE;
        uint32_t bAh = sb, bAl = sb + GTILE, bWh = sb + 2 * GTILE, bWl = sb + 3 * GTILE;
        #pragma unroll
        for (int ks = 0; ks < 2; ++ks) {
            uint32_t koff = ks * 32;
            uint32_t ah[2][4], al[2][4];
            #pragma unroll
            for (int mi = 0; mi < 2; ++mi) {
                LDMX4(ah[mi], bAh + aoff[mi] + koff);
                LDMX4(al[mi], bAl + aoff[mi] + koff);
            }
            #pragma unroll
            for (int p = 0; p < 4; ++p) {
                uint32_t w[4];
                LDMX4(w, bWh + woff[p] + koff);
                mma16816(acc[0][2 * p],     ah[0], w[0], w[1]);
                mma16816(acc[1][2 * p],     ah[1], w[0], w[1]);
                mma16816(acc[0][2 * p + 1], ah[0], w[2], w[3]);
                mma16816(acc[1][2 * p + 1], ah[1], w[2], w[3]);
                mma16816(acc[0][2 * p],     al[0], w[0], w[1]);
                mma16816(acc[1][2 * p],     al[1], w[0], w[1]);
                mma16816(acc[0][2 * p + 1], al[0], w[2], w[3]);
                mma16816(acc[1][2 * p + 1], al[1], w[2], w[3]);
                uint32_t wl[4];
                LDMX4(wl, bWl + woff[p] + koff);
                mma16816(acc[0][2 * p],     ah[0], wl[0], wl[1]);
                mma16816(acc[1][2 * p],     ah[1], wl[0], wl[1]);
                mma16816(acc[0][2 * p + 1], ah[0], wl[2], wl[3]);
                mma16816(acc[1][2 * p + 1], ah[1], wl[2], wl[3]);
            }
        }
    };

    loadChunk(0, 0);
    for (int c = 0; c < C; ++c) {
        if (c + 1 < C) {
            loadChunk(c + 1, (c + 1) & 1);
            asm volatile("cp.async.wait_group 1;" ::: "memory");
        } else {
            asm volatile("cp.async.wait_group 0;" ::: "memory");
        }
        __syncthreads();
        computeChunk(c & 1);
        __syncthreads();
    }

    // ---- epilogue ----
    #pragma unroll
    for (int mi = 0; mi < 2; ++mi) {
        #pragma unroll
        for (int half = 0; half < 2; ++half) {
            int row = rowBase + warpM + mi * 16 + g + half * 8;
            if (row >= M) continue;
            #pragma unroll
            for (int ni = 0; ni < 8; ++ni) {
                int col = colBase + warpN + ni * 8 + 2 * t;
                if (col >= O) continue;
                float v0 = acc[mi][ni][half * 2 + 0];
                float v1 = acc[mi][ni][half * 2 + 1];
                if (BIAS) {
                    float2 bb = *reinterpret_cast<const float2*>(&bias[col]);
                    v0 += bb.x; v1 += bb.y;
                }
                if (RELU) { v0 = fmaxf(v0, 0.f); v1 = fmaxf(v1, 0.f); }
                if (OSPLIT) {
                    // O==128: cols<64 -> Cf[row*64+col]; cols>=64 -> C2 + bias2
                    if (col < 64) {
                        *reinterpret_cast<float2*>(&Cf[(size_t)row * 64 + col]) =
                            make_float2(v0, v1);
                    } else {
                        int c2 = col - 64;
                        float2 bb = *reinterpret_cast<const float2*>(&bias2[c2]);
                        *reinterpret_cast<float2*>(&C2[(size_t)row * 64 + c2]) =
                            make_float2(v0 + bb.x, v1 + bb.y);
                    }
                } else if (BF16OUT) {
                    size_t o = (size_t)row * O + col;
                    uint2 s = split2(v0, v1);
                    *reinterpret_cast<uint32_t*>(&Ch[o]) = s.x;
                    *reinterpret_cast<uint32_t*>(&Cl[o]) = s.y;
                } else {
                    size_t o = (size_t)row * O + col;
                    *reinterpret_cast<float2*>(&Cf[o]) = make_float2(v0, v1);
                }
            }
        }
    }
}

// ---------------- launch ----------------------------------------------------
extern "C" void kernel_launch(void* const* d_in, const int* in_sizes, int n_in,
                              void* d_out, int out_size) {
    const float* x         = (const float*)d_in[0];
    const int*   ei_raw    = (const int*)d_in[1];
    const int*   batch_raw = (const int*)d_in[2];
    const float* W1_rel = (const float*)d_in[3];
    const float* b1     = (const float*)d_in[4];
    const float* W1_root= (const float*)d_in[5];
    const float* W2_rel = (const float*)d_in[6];
    const float* b2     = (const float*)d_in[7];
    const float* W2_root= (const float*)d_in[8];
    const float* W3_rel = (const float*)d_in[9];
    const float* b3     = (const float*)d_in[10];
    const float* W3_root= (const float*)d_in[11];
    const float* W4_rel = (const float*)d_in[12];
    const float* b4     = (const float*)d_in[13];
    const float* W4_root= (const float*)d_in[14];

    float* out = (float*)d_out;
    float* enc = out + (size_t)NNODES * D_IN;

    float *aggx, *aggy, *h2f, *aggh2, *z2, *z4;
    bf16 *x_h, *x_l, *aggx_h, *aggx_l, *h1_h, *h1_l, *h2_h, *h2_l, *ah2_h, *ah2_l;
    bf16 *w1r_h, *w1r_l, *w1o_h, *w1o_l, *w2_h, *w2_l, *w3r_h, *w3r_l, *w3o_h, *w3o_l, *w4_h, *w4_l;
    cudaGetSymbolAddress((void**)&aggx, g_aggx);   cudaGetSymbolAddress((void**)&aggy, g_aggy);
    cudaGetSymbolAddress((void**)&h2f, g_h2f);     cudaGetSymbolAddress((void**)&aggh2, g_aggh2);
    cudaGetSymbolAddress((void**)&z2, g_z2);       cudaGetSymbolAddress((void**)&z4, g_z4);
    cudaGetSymbolAddress((void**)&x_h, g_x_h);     cudaGetSymbolAddress((void**)&x_l, g_x_l);
    cudaGetSymbolAddress((void**)&aggx_h, g_aggx_h); cudaGetSymbolAddress((void**)&aggx_l, g_aggx_l);
    cudaGetSymbolAddress((void**)&h1_h, g_h1_h);   cudaGetSymbolAddress((void**)&h1_l, g_h1_l);
    cudaGetSymbolAddress((void**)&h2_h, g_h2_h);   cudaGetSymbolAddress((void**)&h2_l, g_h2_l);
    cudaGetSymbolAddress((void**)&ah2_h, g_ah2_h); cudaGetSymbolAddress((void**)&ah2_l, g_ah2_l);
    cudaGetSymbolAddress((void**)&w1r_h, g_w1r_h); cudaGetSymbolAddress((void**)&w1r_l, g_w1r_l);
    cudaGetSymbolAddress((void**)&w1o_h, g_w1o_h); cudaGetSymbolAddress((void**)&w1o_l, g_w1o_l);
    cudaGetSymbolAddress((void**)&w2_h, g_w2_h);   cudaGetSymbolAddress((void**)&w2_l, g_w2_l);
    cudaGetSymbolAddress((void**)&w3r_h, g_w3r_h); cudaGetSymbolAddress((void**)&w3r_l, g_w3r_l);
    cudaGetSymbolAddress((void**)&w3o_h, g_w3o_h); cudaGetSymbolAddress((void**)&w3o_l, g_w3o_l);
    cudaGetSymbolAddress((void**)&w4_h, g_w4_h);   cudaGetSymbolAddress((void**)&w4_l, g_w4_l);

    const int T = 256;
    const int MB = (NNODES + 127) / 128;   // 391
    constexpr int SMEM = 2 * GSTAGE;       // 81920

    cudaFuncSetAttribute(mmagemm<true,  true,  true,  true,  false>, cudaFuncAttributeMaxDynamicSharedMemorySize, SMEM);
    cudaFuncSetAttribute(mmagemm<false, false, false, false, false>, cudaFuncAttributeMaxDynamicSharedMemorySize, SMEM);
    cudaFuncSetAttribute(mmagemm<false, false, false, false, true >, cudaFuncAttributeMaxDynamicSharedMemorySize, SMEM);

    // ---- setup: index convert (inline detect) + zero + weight/x split
    convert_kernel<<<(2 * NEDGES + T - 1) / T, T>>>(ei_raw, batch_raw);
    setup_kernel<<<1024, T>>>(W1_rel, W1_root, W2_rel, W2_root,
                              W3_rel, W3_root, W4_rel, W4_root, x);

    // ---- L1: agg(x) then dual-A MMA -> h1 (bf16 hi/lo, relu, bias)
    edge_agg_kernel<64><<<(NEDGES * 8 + T - 1) / T, T>>>(x, D_IN, aggx, D_IN);
    split_kernel<<<512, T>>>(aggx, aggx_h, aggx_l, NNODES * D_IN);
    {
        dim3 grid((D_H + 127) / 128, MB);
        mmagemm<true, true, true, true, false><<<grid, T, SMEM>>>(
            nullptr, h1_h, h1_l,
            aggx_h, aggx_l, x_h, x_l,
            w1r_h, w1r_l, w1o_h, w1o_l,
            b1, NNODES, D_IN, D_H, nullptr, nullptr);
    }

    // ---- L2: single-A MMA (K=1000, O=256 cat) -> z2 fp32
    {
        dim3 grid(2, MB);
        mmagemm<false, false, false, false, false><<<grid, T, SMEM>>>(
            z2, nullptr, nullptr,
            h1_h, h1_l, nullptr, nullptr,
            w2_h, w2_l, nullptr, nullptr,
            nullptr, NNODES, D_H, 256, nullptr, nullptr);
    }
    edge_agg_kernel<128><<<(NEDGES * 16 + T - 1) / T, T>>>(z2, 256, aggy, D_ENC);
    combine_pool_kernel<<<(NNODES * 32 + T - 1) / T, T>>>(b2);
    encoded_kernel<<<(NGRAPH * D_ENC + T - 1) / T, T>>>(enc);

    // ---- L3: agg(h2) then dual-A MMA -> h3 (reuse h1 buffers)
    edge_agg_kernel<128><<<(NEDGES * 16 + T - 1) / T, T>>>(h2f, D_ENC, aggh2, D_ENC);
    split_kernel<<<512, T>>>(aggh2, ah2_h, ah2_l, NNODES * D_ENC);
    {
        dim3 grid((D_H + 127) / 128, MB);
        mmagemm<true, true, true, true, false><<<grid, T, SMEM>>>(
            nullptr, h1_h, h1_l,
            ah2_h, ah2_l, h2_h, h2_l,
            w3r_h, w3r_l, w3o_h, w3o_l,
            b3, NNODES, D_ENC, D_H, nullptr, nullptr);
    }

    // ---- L4: single-A MMA (K=1000, O=128 cat); rel half -> z4, root+b4 -> out
    {
        dim3 grid(1, MB);
        mmagemm<false, false, false, false, true><<<grid, T, SMEM>>>(
            z4, nullptr, nullptr,
            h1_h, h1_l, nullptr, nullptr,
            w4_h, w4_l, nullptr, nullptr,
            nullptr, NNODES, D_H, 128, out, b4);
    }
    edge_agg_kernel<64><<<(NEDGES * 8 + T - 1) / T, T>>>(z4, 64, out, D_IN);
}

// round 11
// speedup vs baseline: 1.1699x; 1.1699x over previous
#include <cuda_runtime.h>
#include <cuda_bf16.h>
#include <cstdint>

#define NNODES 50000
#define NEDGES 200000
#define NGRAPH 2048
#define D_IN   64
#define D_H    1000
#define D_ENC  128

typedef __nv_bfloat16 bf16;

// ---------------- scratch (static device allocations; no cudaMalloc) --------
__device__ float g_aggx [NNODES * D_IN];
__device__ float g_aggy [NNODES * D_ENC];
__device__ float g_h2f  [NNODES * D_ENC];
__device__ float g_aggh2[NNODES * D_ENC];
__device__ float g_z2   [NNODES * 256];   // cols 0..127 rel, 128..255 root
__device__ float g_z4   [NNODES * 64];    // z4 rel half only (root fused into out)
__device__ float g_sums [NGRAPH * D_ENC];
__device__ float g_counts[NGRAPH];
__device__ int   g_ei32[2 * NEDGES];
__device__ int   g_batch32[NNODES];
__device__ int   g_is64;

__device__ __align__(16) bf16 g_x_h   [NNODES * D_IN],  g_x_l   [NNODES * D_IN];
__device__ __align__(16) bf16 g_aggx_h[NNODES * D_IN],  g_aggx_l[NNODES * D_IN];
__device__ __align__(16) bf16 g_h1_h  [(size_t)NNODES * D_H], g_h1_l[(size_t)NNODES * D_H];
__device__ __align__(16) bf16 g_h2_h  [NNODES * D_ENC], g_h2_l [NNODES * D_ENC];
__device__ __align__(16) bf16 g_ah2_h [NNODES * D_ENC], g_ah2_l[NNODES * D_ENC];
__device__ __align__(16) bf16 g_w1r_h[D_H * D_IN],  g_w1r_l[D_H * D_IN];
__device__ __align__(16) bf16 g_w1o_h[D_H * D_IN],  g_w1o_l[D_H * D_IN];
__device__ __align__(16) bf16 g_w2_h [256 * D_H],   g_w2_l [256 * D_H];
__device__ __align__(16) bf16 g_w3r_h[D_H * D_ENC], g_w3r_l[D_H * D_ENC];
__device__ __align__(16) bf16 g_w3o_h[D_H * D_ENC], g_w3o_l[D_H * D_ENC];
__device__ __align__(16) bf16 g_w4_h [128 * D_H],   g_w4_l [128 * D_H];

// ---------------- helpers ----------------------------------------------------
__device__ __forceinline__ uint2 split2(float v0, float v1) {
    uint32_t pH;
    asm("cvt.rn.bf16x2.f32 %0, %1, %2;" : "=r"(pH) : "f"(v1), "f"(v0));
    float h0 = __uint_as_float(pH << 16);
    float h1 = __uint_as_float(pH & 0xffff0000u);
    float r0 = v0 - h0, r1 = v1 - h1;
    uint32_t pL;
    asm("cvt.rn.bf16x2.f32 %0, %1, %2;" : "=r"(pL) : "f"(r1), "f"(r0));
    return make_uint2(pH, pL);
}
__device__ __forceinline__ void mma16816(float* d, const uint32_t* a, uint32_t b0, uint32_t b1) {
    asm volatile(
        "mma.sync.aligned.m16n8k16.row.col.f32.bf16.bf16.f32 "
        "{%0,%1,%2,%3}, {%4,%5,%6,%7}, {%8,%9}, {%0,%1,%2,%3};"
        : "+f"(d[0]), "+f"(d[1]), "+f"(d[2]), "+f"(d[3])
        : "r"(a[0]), "r"(a[1]), "r"(a[2]), "r"(a[3]), "r"(b0), "r"(b1));
}
__device__ __forceinline__ uint32_t cvta_s(const void* p) {
    uint32_t a;
    asm("{ .reg .u64 t; cvta.to.shared.u64 t, %1; cvt.u32.u64 %0, t; }" : "=r"(a) : "l"(p));
    return a;
}
#define LDMX4(r, a) \
    asm volatile("ldmatrix.sync.aligned.m8n8.x4.shared.b16 {%0,%1,%2,%3}, [%4];" \
        : "=r"((r)[0]), "=r"((r)[1]), "=r"((r)[2]), "=r"((r)[3]) : "r"(a))

// ---------------- dtype detection + conversion ------------------------------
__global__ void detect_kernel(const int* __restrict__ ei_raw) {
    int odd_zero = 1;
    #pragma unroll
    for (int i = 0; i < 16; ++i)
        if (ei_raw[2 * i + 1] != 0) odd_zero = 0;
    g_is64 = odd_zero;
}
__global__ void convert_kernel(const int* __restrict__ ei_raw, const int* __restrict__ batch_raw) {
    int i = blockIdx.x * blockDim.x + threadIdx.x;
    int is64 = g_is64;
    if (i < 2 * NEDGES) g_ei32[i] = is64 ? ei_raw[2 * i] : ei_raw[i];
    if (i < NNODES)     g_batch32[i] = is64 ? batch_raw[2 * i] : batch_raw[i];
}

// ---------------- merged utility kernels -------------------------------------
__global__ void zero_all_kernel() {
    float4 z = make_float4(0.f, 0.f, 0.f, 0.f);
    float4* aggy  = reinterpret_cast<float4*>(g_aggy);
    float4* aggh2 = reinterpret_cast<float4*>(g_aggh2);
    float4* aggx  = reinterpret_cast<float4*>(g_aggx);
    float4* sums  = reinterpret_cast<float4*>(g_sums);
    float4* cnts  = reinterpret_cast<float4*>(g_counts);
    for (int i = blockIdx.x * blockDim.x + threadIdx.x; i < NNODES * D_ENC / 4;
         i += gridDim.x * blockDim.x) {
        aggy[i] = z;
        aggh2[i] = z;
        if (i < NNODES * D_IN / 4) aggx[i] = z;
        if (i < NGRAPH * D_ENC / 4) sums[i] = z;
        if (i < NGRAPH / 4) cnts[i] = z;
    }
}
// split all weights + x in one launch; 2 elements per iteration
__global__ void split_static_kernel(
    const float* __restrict__ w1r, const float* __restrict__ w1o,
    const float* __restrict__ w2r, const float* __restrict__ w2o,
    const float* __restrict__ w3r, const float* __restrict__ w3o,
    const float* __restrict__ w4r, const float* __restrict__ w4o,
    const float* __restrict__ x) {
    const int H1 = D_H * D_IN / 2;
    const int H2 = 128 * D_H / 2;
    const int H3 = D_H * D_ENC / 2;
    const int H4 = 64 * D_H / 2;
    const int HX = NNODES * D_IN / 2;
    const int TOTP = 2 * H1 + 2 * H2 + 2 * H3 + 2 * H4 + HX;
    for (int p = blockIdx.x * blockDim.x + threadIdx.x; p < TOTP;
         p += gridDim.x * blockDim.x) {
        const float* src; bf16 *dh, *dl; int j = p;
        if (j < H1)              { src = w1r; dh = g_w1r_h; dl = g_w1r_l; }
        else if ((j -= H1) < H1) { src = w1o; dh = g_w1o_h; dl = g_w1o_l; }
        else if ((j -= H1) < H2) { src = w2r; dh = g_w2_h; dl = g_w2_l; }
        else if ((j -= H2) < H2) { src = w2o; dh = g_w2_h + 2 * H2; dl = g_w2_l + 2 * H2; }
        else if ((j -= H2) < H3) { src = w3r; dh = g_w3r_h; dl = g_w3r_l; }
        else if ((j -= H3) < H3) { src = w3o; dh = g_w3o_h; dl = g_w3o_l; }
        else if ((j -= H3) < H4) { src = w4r; dh = g_w4_h; dl = g_w4_l; }
        else if ((j -= H4) < H4) { src = w4o; dh = g_w4_h + 2 * H4; dl = g_w4_l + 2 * H4; }
        else { j -= H4;            src = x;   dh = g_x_h;  dl = g_x_l; }
        int e = j * 2;
        float2 v = *reinterpret_cast<const float2*>(&src[e]);
        uint2 s = split2(v.x, v.y);
        *reinterpret_cast<uint32_t*>(&dh[e]) = s.x;
        *reinterpret_cast<uint32_t*>(&dl[e]) = s.y;
    }
}
__global__ void split_kernel(const float* __restrict__ src, bf16* __restrict__ hi,
                             bf16* __restrict__ lo, int n) {
    for (int e = (blockIdx.x * blockDim.x + threadIdx.x) * 2; e < n;
         e += gridDim.x * blockDim.x * 2) {
        float2 v = *reinterpret_cast<const float2*>(&src[e]);
        uint2 s = split2(v.x, v.y);
        *reinterpret_cast<uint32_t*>(&hi[e]) = s.x;
        *reinterpret_cast<uint32_t*>(&lo[e]) = s.y;
    }
}
// segment-sum over edges: 4 features per thread (R9-proven config)
template <int F>
__global__ void edge_agg_kernel(const float* __restrict__ feat, int featStride,
                                float* __restrict__ out, int outStride) {
    constexpr int V = F / 4;
    int idx = blockIdx.x * blockDim.x + threadIdx.x;
    int e = idx / V;
    int f = (idx % V) * 4;
    if (e >= NEDGES) return;
    int s = g_ei32[e];
    int d = g_ei32[NEDGES + e];
    float4 v = *reinterpret_cast<const float4*>(&feat[(size_t)s * featStride + f]);
    float* o = &out[(size_t)d * outStride + f];
    atomicAdd(o + 0, v.x); atomicAdd(o + 1, v.y);
    atomicAdd(o + 2, v.z); atomicAdd(o + 3, v.w);
}
// fused: h2 = relu(aggy + z2_root + b2); fp32 + packed hi/lo; pool (2 el/thread)
__global__ void combine_pool_kernel(const float* __restrict__ b2) {
    int idx = blockIdx.x * blockDim.x + threadIdx.x;
    if (idx >= NNODES * 64) return;
    int i = idx >> 6, f = (idx & 63) * 2;
    float2 ag = *reinterpret_cast<const float2*>(&g_aggy[i * D_ENC + f]);
    float2 zr = *reinterpret_cast<const float2*>(&g_z2[(size_t)i * 256 + 128 + f]);
    float2 bb = *reinterpret_cast<const float2*>(&b2[f]);
    float v0 = fmaxf(ag.x + zr.x + bb.x, 0.f);
    float v1 = fmaxf(ag.y + zr.y + bb.y, 0.f);
    *reinterpret_cast<float2*>(&g_h2f[i * D_ENC + f]) = make_float2(v0, v1);
    uint2 s = split2(v0, v1);
    *reinterpret_cast<uint32_t*>(&g_h2_h[i * D_ENC + f]) = s.x;
    *reinterpret_cast<uint32_t*>(&g_h2_l[i * D_ENC + f]) = s.y;
    int b = g_batch32[i];
    atomicAdd(&g_sums[b * D_ENC + f], v0);
    atomicAdd(&g_sums[b * D_ENC + f + 1], v1);
    if (f == 0) atomicAdd(&g_counts[b], 1.f);
}
__global__ void encoded_kernel(float* __restrict__ enc) {
    int idx = blockIdx.x * blockDim.x + threadIdx.x;
    if (idx >= NGRAPH * D_ENC) return;
    int g = idx >> 7;
    enc[idx] = g_sums[idx] / fmaxf(g_counts[g], 1.f);
}

// ---------------- pipelined mma.sync bf16x3 GEMM (R6/R9 config) --------------
// block 128x128; 8 warps (4m x 2n); warp tile 32x64.
// K-chunk 32, 2-stage cp.async pipeline, ldmatrix.x4 fragment loads, 2 CTA/SM.
#define CHUNK 32
#define SROW  80
#define GTILE (128 * SROW)        // 10240
#define GSTAGE (4 * GTILE)        // 40960

template <bool DUAL_A, bool RELU, bool BIAS, bool BF16OUT, bool OSPLIT>
__global__ void __launch_bounds__(256, 2) mmagemm(
    float* __restrict__ Cf, bf16* __restrict__ Ch, bf16* __restrict__ Cl,
    const bf16* __restrict__ A1h, const bf16* __restrict__ A1l,
    const bf16* __restrict__ A2h, const bf16* __restrict__ A2l,
    const bf16* __restrict__ B1h, const bf16* __restrict__ B1l,
    const bf16* __restrict__ B2h, const bf16* __restrict__ B2l,
    const float* __restrict__ bias, int M, int K, int O,
    float* __restrict__ C2, const float* __restrict__ bias2) {

    extern __shared__ char smraw[];
    const uint32_t smemBase = cvta_s(smraw);

    const int tid = threadIdx.x;
    const int wid = tid >> 5, lane = tid & 31;
    const int g = lane >> 2, t = lane & 3;
    const int warpM = (wid & 3) * 32, warpN = (wid >> 2) * 64;
    const int rowBase = blockIdx.y * 128, colBase = blockIdx.x * 128;

    const int laneRowA = (lane & 7) + ((lane & 8) ? 8 : 0);
    const int aK = (lane & 16) ? 16 : 0;
    const int laneRowW = (lane & 7) + ((lane & 16) ? 8 : 0);
    const int wK = (lane & 8) ? 16 : 0;
    uint32_t aoff[2], woff[4];
    #pragma unroll
    for (int mi = 0; mi < 2; ++mi)
        aoff[mi] = (uint32_t)((warpM + mi * 16 + laneRowA) * SROW + aK);
    #pragma unroll
    for (int p = 0; p < 4; ++p)
        woff[p] = (uint32_t)((warpN + p * 16 + laneRowW) * SROW + wK);

    float acc[2][8][4];
    #pragma unroll
    for (int a = 0; a < 2; ++a)
        #pragma unroll
        for (int b = 0; b < 8; ++b)
            #pragma unroll
            for (int c = 0; c < 4; ++c) acc[a][b][c] = 0.f;

    const int KC = (K + CHUNK - 1) / CHUNK;
    const int C = (DUAL_A ? 2 : 1) * KC;

    auto loadChunk = [&](int i, int stage) {
        int sIdx = DUAL_A ? (i / KC) : 0;
        int c = i - sIdx * KC;
        int k0 = c * CHUNK;
        const bf16* Ah = (DUAL_A && sIdx) ? A2h : A1h;
        const bf16* Al = (DUAL_A && sIdx) ? A2l : A1l;
        const bf16* Wh = (DUAL_A && sIdx) ? B2h : B1h;
        const bf16* Wl = (DUAL_A && sIdx) ? B2l : B1l;
        uint32_t sb = smemBase + stage * GSTAGE;
        #pragma unroll
        for (int j = 0; j < 8; ++j) {
            int idx = tid + j * 256;
            int tile = idx >> 9;
            int r = (idx >> 2) & 127;
            int sg = idx & 3;
            int gk = k0 + sg * 8;
            const bf16* src;
            int ok;
            if (tile < 2) {
                int gr = rowBase + r;
                ok = (gr < M) && (gk + 8 <= K);
                const bf16* base = tile ? Al : Ah;
                src = ok ? base + (size_t)gr * K + gk : base;
            } else {
                int gw = colBase + r;
                ok = (gw < O) && (gk + 8 <= K);
                const bf16* base = (tile == 2) ? Wh : Wl;
                src = ok ? base + (size_t)gw * K + gk : base;
            }
            uint32_t dst = sb + tile * GTILE + (uint32_t)(r * SROW + sg * 16);
            int sz = ok ? 16 : 0;
            asm volatile("cp.async.cg.shared.global [%0], [%1], 16, %2;"
                         :: "r"(dst), "l"(src), "r"(sz) : "memory");
        }
        asm volatile("cp.async.commit_group;" ::: "memory");
    };

    auto computeChunk = [&](int stage) {
        uint32_t sb = smemBase + stage * GSTAGE;
        uint32_t bAh = sb, bAl = sb + GTILE, bWh = sb + 2 * GTILE, bWl = sb + 3 * GTILE;
        #pragma unroll
        for (int ks = 0; ks < 2; ++ks) {
            uint32_t koff = ks * 32;
            uint32_t ah[2][4], al[2][4];
            #pragma unroll
            for (int mi = 0; mi < 2; ++mi) {
                LDMX4(ah[mi], bAh + aoff[mi] + koff);
                LDMX4(al[mi], bAl + aoff[mi] + koff);
            }
            #pragma unroll
            for (int p = 0; p < 4; ++p) {
                uint32_t w[4];
                LDMX4(w, bWh + woff[p] + koff);
                mma16816(acc[0][2 * p],     ah[0], w[0], w[1]);
                mma16816(acc[1][2 * p],     ah[1], w[0], w[1]);
                mma16816(acc[0][2 * p + 1], ah[0], w[2], w[3]);
                mma16816(acc[1][2 * p + 1], ah[1], w[2], w[3]);
                mma16816(acc[0][2 * p],     al[0], w[0], w[1]);
                mma16816(acc[1][2 * p],     al[1], w[0], w[1]);
                mma16816(acc[0][2 * p + 1], al[0], w[2], w[3]);
                mma16816(acc[1][2 * p + 1], al[1], w[2], w[3]);
                uint32_t wl[4];
                LDMX4(wl, bWl + woff[p] + koff);
                mma16816(acc[0][2 * p],     ah[0], wl[0], wl[1]);
                mma16816(acc[1][2 * p],     ah[1], wl[0], wl[1]);
                mma16816(acc[0][2 * p + 1], ah[0], wl[2], wl[3]);
                mma16816(acc[1][2 * p + 1], ah[1], wl[2], wl[3]);
            }
        }
    };

    loadChunk(0, 0);
    for (int c = 0; c < C; ++c) {
        if (c + 1 < C) {
            loadChunk(c + 1, (c + 1) & 1);
            asm volatile("cp.async.wait_group 1;" ::: "memory");
        } else {
            asm volatile("cp.async.wait_group 0;" ::: "memory");
        }
        __syncthreads();
        computeChunk(c & 1);
        __syncthreads();
    }

    // ---- epilogue (cols always even; pair stores unconditional) ----
    #pragma unroll
    for (int mi = 0; mi < 2; ++mi) {
        #pragma unroll
        for (int half = 0; half < 2; ++half) {
            int row = rowBase + warpM + mi * 16 + g + half * 8;
            if (row >= M) continue;
            #pragma unroll
            for (int ni = 0; ni < 8; ++ni) {
                int col = colBase + warpN + ni * 8 + 2 * t;
                if (col >= O) continue;
                float v0 = acc[mi][ni][half * 2 + 0];
                float v1 = acc[mi][ni][half * 2 + 1];
                if (BIAS) {
                    float2 bb = *reinterpret_cast<const float2*>(&bias[col]);
                    v0 += bb.x; v1 += bb.y;
                }
                if (RELU) { v0 = fmaxf(v0, 0.f); v1 = fmaxf(v1, 0.f); }
                if (OSPLIT) {
                    // O==128: cols<64 -> Cf[row*64+col] (rel); cols>=64 -> C2 + bias2 (root)
                    if (col < 64) {
                        *reinterpret_cast<float2*>(&Cf[(size_t)row * 64 + col]) =
                            make_float2(v0, v1);
                    } else {
                        int c2 = col - 64;
                        float2 bb = *reinterpret_cast<const float2*>(&bias2[c2]);
                        *reinterpret_cast<float2*>(&C2[(size_t)row * 64 + c2]) =
                            make_float2(v0 + bb.x, v1 + bb.y);
                    }
                } else if (BF16OUT) {
                    size_t o = (size_t)row * O + col;
                    uint2 s = split2(v0, v1);
                    *reinterpret_cast<uint32_t*>(&Ch[o]) = s.x;
                    *reinterpret_cast<uint32_t*>(&Cl[o]) = s.y;
                } else {
                    size_t o = (size_t)row * O + col;
                    *reinterpret_cast<float2*>(&Cf[o]) = make_float2(v0, v1);
                }
            }
        }
    }
}

// ---------------- launch ----------------------------------------------------
extern "C" void kernel_launch(void* const* d_in, const int* in_sizes, int n_in,
                              void* d_out, int out_size) {
    const float* x         = (const float*)d_in[0];
    const int*   ei_raw    = (const int*)d_in[1];
    const int*   batch_raw = (const int*)d_in[2];
    const float* W1_rel = (const float*)d_in[3];
    const float* b1     = (const float*)d_in[4];
    const float* W1_root= (const float*)d_in[5];
    const float* W2_rel = (const float*)d_in[6];
    const float* b2     = (const float*)d_in[7];
    const float* W2_root= (const float*)d_in[8];
    const float* W3_rel = (const float*)d_in[9];
    const float* b3     = (const float*)d_in[10];
    const float* W3_root= (const float*)d_in[11];
    const float* W4_rel = (const float*)d_in[12];
    const float* b4     = (const float*)d_in[13];
    const float* W4_root= (const float*)d_in[14];

    float* out = (float*)d_out;
    float* enc = out + (size_t)NNODES * D_IN;

    float *aggx, *aggy, *h2f, *aggh2, *z2, *z4;
    bf16 *x_h, *x_l, *aggx_h, *aggx_l, *h1_h, *h1_l, *h2_h, *h2_l, *ah2_h, *ah2_l;
    bf16 *w1r_h, *w1r_l, *w1o_h, *w1o_l, *w2_h, *w2_l, *w3r_h, *w3r_l, *w3o_h, *w3o_l, *w4_h, *w4_l;
    cudaGetSymbolAddress((void**)&aggx, g_aggx);   cudaGetSymbolAddress((void**)&aggy, g_aggy);
    cudaGetSymbolAddress((void**)&h2f, g_h2f);     cudaGetSymbolAddress((void**)&aggh2, g_aggh2);
    cudaGetSymbolAddress((void**)&z2, g_z2);       cudaGetSymbolAddress((void**)&z4, g_z4);
    cudaGetSymbolAddress((void**)&x_h, g_x_h);     cudaGetSymbolAddress((void**)&x_l, g_x_l);
    cudaGetSymbolAddress((void**)&aggx_h, g_aggx_h); cudaGetSymbolAddress((void**)&aggx_l, g_aggx_l);
    cudaGetSymbolAddress((void**)&h1_h, g_h1_h);   cudaGetSymbolAddress((void**)&h1_l, g_h1_l);
    cudaGetSymbolAddress((void**)&h2_h, g_h2_h);   cudaGetSymbolAddress((void**)&h2_l, g_h2_l);
    cudaGetSymbolAddress((void**)&ah2_h, g_ah2_h); cudaGetSymbolAddress((void**)&ah2_l, g_ah2_l);
    cudaGetSymbolAddress((void**)&w1r_h, g_w1r_h); cudaGetSymbolAddress((void**)&w1r_l, g_w1r_l);
    cudaGetSymbolAddress((void**)&w1o_h, g_w1o_h); cudaGetSymbolAddress((void**)&w1o_l, g_w1o_l);
    cudaGetSymbolAddress((void**)&w2_h, g_w2_h);   cudaGetSymbolAddress((void**)&w2_l, g_w2_l);
    cudaGetSymbolAddress((void**)&w3r_h, g_w3r_h); cudaGetSymbolAddress((void**)&w3r_l, g_w3r_l);
    cudaGetSymbolAddress((void**)&w3o_h, g_w3o_h); cudaGetSymbolAddress((void**)&w3o_l, g_w3o_l);
    cudaGetSymbolAddress((void**)&w4_h, g_w4_h);   cudaGetSymbolAddress((void**)&w4_l, g_w4_l);

    const int T = 256;
    const int MB = (NNODES + 127) / 128;   // 391
    constexpr int SMEM = 2 * GSTAGE;       // 81920

    cudaFuncSetAttribute(mmagemm<true,  true,  true,  true,  false>, cudaFuncAttributeMaxDynamicSharedMemorySize, SMEM);
    cudaFuncSetAttribute(mmagemm<false, false, false, false, false>, cudaFuncAttributeMaxDynamicSharedMemorySize, SMEM);
    cudaFuncSetAttribute(mmagemm<false, false, false, false, true >, cudaFuncAttributeMaxDynamicSharedMemorySize, SMEM);

    // ---- setup
    detect_kernel<<<1, 1>>>(ei_raw);
    convert_kernel<<<(2 * NEDGES + T - 1) / T, T>>>(ei_raw, batch_raw);
    zero_all_kernel<<<1024, T>>>();
    split_static_kernel<<<1024, T>>>(W1_rel, W1_root, W2_rel, W2_root,
                                     W3_rel, W3_root, W4_rel, W4_root, x);

    // ---- L1: agg(x) then dual-A MMA -> h1 (bf16 hi/lo, relu, bias)
    edge_agg_kernel<64><<<(NEDGES * 16 + T - 1) / T, T>>>(x, D_IN, aggx, D_IN);
    split_kernel<<<512, T>>>(aggx, aggx_h, aggx_l, NNODES * D_IN);
    {
        dim3 grid((D_H + 127) / 128, MB);
        mmagemm<true, true, true, true, false><<<grid, T, SMEM>>>(
            nullptr, h1_h, h1_l,
            aggx_h, aggx_l, x_h, x_l,
            w1r_h, w1r_l, w1o_h, w1o_l,
            b1, NNODES, D_IN, D_H, nullptr, nullptr);
    }

    // ---- L2: single-A MMA (K=1000, O=256 cat) -> z2 fp32
    {
        dim3 grid(2, MB);
        mmagemm<false, false, false, false, false><<<grid, T, SMEM>>>(
            z2, nullptr, nullptr,
            h1_h, h1_l, nullptr, nullptr,
            w2_h, w2_l, nullptr, nullptr,
            nullptr, NNODES, D_H, 256, nullptr, nullptr);
    }
    edge_agg_kernel<128><<<(NEDGES * 32 + T - 1) / T, T>>>(z2, 256, aggy, D_ENC);
    combine_pool_kernel<<<(NNODES * 64 + T - 1) / T, T>>>(b2);
    encoded_kernel<<<(NGRAPH * D_ENC + T - 1) / T, T>>>(enc);

    // ---- L3: agg(h2) then dual-A MMA -> h3 (reuse h1 buffers)
    edge_agg_kernel<128><<<(NEDGES * 32 + T - 1) / T, T>>>(h2f, D_ENC, aggh2, D_ENC);
    split_kernel<<<512, T>>>(aggh2, ah2_h, ah2_l, NNODES * D_ENC);
    {
        dim3 grid((D_H + 127) / 128, MB);
        mmagemm<true, true, true, true, false><<<grid, T, SMEM>>>(
            nullptr, h1_h, h1_l,
            ah2_h, ah2_l, h2_h, h2_l,
            w3r_h, w3r_l, w3o_h, w3o_l,
            b3, NNODES, D_ENC, D_H, nullptr, nullptr);
    }

    // ---- L4: single-A MMA (K=1000, O=128 cat); rel half -> z4, root+b4 -> out
    {
        dim3 grid(1, MB);
        mmagemm<false, false, false, false, true><<<grid, T, SMEM>>>(
            z4, nullptr, nullptr,
            h1_h, h1_l, nullptr, nullptr,
            w4_h, w4_l, nullptr, nullptr,
            nullptr, NNODES, D_H, 128, out, b4);
    }
    edge_agg_kernel<64><<<(NEDGES * 16 + T - 1) / T, T>>>(z4, 64, out, D_IN);
}

// round 12
// speedup vs baseline: 1.4970x; 1.2796x over previous
#include <cuda_runtime.h>
#include <cuda_fp16.h>
#include <cstdint>

#define NNODES 50000
#define NEDGES 200000
#define NGRAPH 2048
#define D_IN   64
#define D_H    1000
#define D_ENC  128

typedef __half f16;

// ---------------- scratch (static device allocations; no cudaMalloc) --------
__device__ float g_aggx [NNODES * D_IN];
__device__ float g_aggy [NNODES * D_ENC];
__device__ float g_h2f  [NNODES * D_ENC];
__device__ float g_aggh2[NNODES * D_ENC];
__device__ float g_z2   [NNODES * 256];   // cols 0..127 rel, 128..255 root
__device__ float g_z4   [NNODES * 64];    // z4 rel half only (root fused into out)
__device__ float g_sums [NGRAPH * D_ENC];
__device__ float g_counts[NGRAPH];
__device__ int   g_ei32[2 * NEDGES];
__device__ int   g_batch32[NNODES];
__device__ int   g_is64;

// fp16 activation operands (single) and weight hi/lo pairs
__device__ __align__(16) f16 g_x16   [NNODES * D_IN];
__device__ __align__(16) f16 g_aggx16[NNODES * D_IN];
__device__ __align__(16) f16 g_h116  [(size_t)NNODES * D_H];
__device__ __align__(16) f16 g_h216  [NNODES * D_ENC];
__device__ __align__(16) f16 g_ah216 [NNODES * D_ENC];
__device__ __align__(16) f16 g_w1r_h[D_H * D_IN],  g_w1r_l[D_H * D_IN];
__device__ __align__(16) f16 g_w1o_h[D_H * D_IN],  g_w1o_l[D_H * D_IN];
__device__ __align__(16) f16 g_w2_h [256 * D_H],   g_w2_l [256 * D_H];
__device__ __align__(16) f16 g_w3r_h[D_H * D_ENC], g_w3r_l[D_H * D_ENC];
__device__ __align__(16) f16 g_w3o_h[D_H * D_ENC], g_w3o_l[D_H * D_ENC];
__device__ __align__(16) f16 g_w4_h [128 * D_H],   g_w4_l [128 * D_H];

// ---------------- helpers ----------------------------------------------------
// pack two floats into f16x2 (element0 in low 16 bits)
__device__ __forceinline__ uint32_t pack2h(float v0, float v1) {
    uint32_t p;
    asm("cvt.rn.f16x2.f32 %0, %1, %2;" : "=r"(p) : "f"(v1), "f"(v0));
    return p;
}
// weight hi/lo split in fp16
__device__ __forceinline__ uint2 split2h(float v0, float v1) {
    uint32_t pH = pack2h(v0, v1);
    __half2 hv = *reinterpret_cast<__half2*>(&pH);
    float h0 = __low2float(hv);
    float h1 = __high2float(hv);
    uint32_t pL = pack2h(v0 - h0, v1 - h1);
    return make_uint2(pH, pL);
}
__device__ __forceinline__ void mma16816(float* d, const uint32_t* a, uint32_t b0, uint32_t b1) {
    asm volatile(
        "mma.sync.aligned.m16n8k16.row.col.f32.f16.f16.f32 "
        "{%0,%1,%2,%3}, {%4,%5,%6,%7}, {%8,%9}, {%0,%1,%2,%3};"
        : "+f"(d[0]), "+f"(d[1]), "+f"(d[2]), "+f"(d[3])
        : "r"(a[0]), "r"(a[1]), "r"(a[2]), "r"(a[3]), "r"(b0), "r"(b1));
}
__device__ __forceinline__ uint32_t cvta_s(const void* p) {
    uint32_t a;
    asm("{ .reg .u64 t; cvta.to.shared.u64 t, %1; cvt.u32.u64 %0, t; }" : "=r"(a) : "l"(p));
    return a;
}
#define LDMX4(r, a) \
    asm volatile("ldmatrix.sync.aligned.m8n8.x4.shared.b16 {%0,%1,%2,%3}, [%4];" \
        : "=r"((r)[0]), "=r"((r)[1]), "=r"((r)[2]), "=r"((r)[3]) : "r"(a))

// ---------------- dtype detection + conversion ------------------------------
__global__ void detect_kernel(const int* __restrict__ ei_raw) {
    int odd_zero = 1;
    #pragma unroll
    for (int i = 0; i < 16; ++i)
        if (ei_raw[2 * i + 1] != 0) odd_zero = 0;
    g_is64 = odd_zero;
}
__global__ void convert_kernel(const int* __restrict__ ei_raw, const int* __restrict__ batch_raw) {
    int i = blockIdx.x * blockDim.x + threadIdx.x;
    int is64 = g_is64;
    if (i < 2 * NEDGES) g_ei32[i] = is64 ? ei_raw[2 * i] : ei_raw[i];
    if (i < NNODES)     g_batch32[i] = is64 ? batch_raw[2 * i] : batch_raw[i];
}

// ---------------- merged utility kernels -------------------------------------
__global__ void zero_all_kernel() {
    float4 z = make_float4(0.f, 0.f, 0.f, 0.f);
    float4* aggy  = reinterpret_cast<float4*>(g_aggy);
    float4* aggh2 = reinterpret_cast<float4*>(g_aggh2);
    float4* aggx  = reinterpret_cast<float4*>(g_aggx);
    float4* sums  = reinterpret_cast<float4*>(g_sums);
    float4* cnts  = reinterpret_cast<float4*>(g_counts);
    for (int i = blockIdx.x * blockDim.x + threadIdx.x; i < NNODES * D_ENC / 4;
         i += gridDim.x * blockDim.x) {
        aggy[i] = z;
        aggh2[i] = z;
        if (i < NNODES * D_IN / 4) aggx[i] = z;
        if (i < NGRAPH * D_ENC / 4) sums[i] = z;
        if (i < NGRAPH / 4) cnts[i] = z;
    }
}
// weights -> fp16 hi/lo; x -> fp16 single. one launch, 2 elements/iteration.
__global__ void split_static_kernel(
    const float* __restrict__ w1r, const float* __restrict__ w1o,
    const float* __restrict__ w2r, const float* __restrict__ w2o,
    const float* __restrict__ w3r, const float* __restrict__ w3o,
    const float* __restrict__ w4r, const float* __restrict__ w4o,
    const float* __restrict__ x) {
    const int P1 = D_H * D_IN / 2;     // 32000
    const int P2 = 128 * D_H / 2;      // 64000
    const int P3 = D_H * D_ENC / 2;    // 64000
    const int P4 = 64 * D_H / 2;       // 32000
    const int PX = NNODES * D_IN / 2;  // 1600000
    const int TOTP = 2 * P1 + 2 * P2 + 2 * P3 + 2 * P4 + PX;
    for (int p = blockIdx.x * blockDim.x + threadIdx.x; p < TOTP;
         p += gridDim.x * blockDim.x) {
        const float* src; f16 *dh = nullptr, *dl = nullptr; int j = p;
        if (j < P1)              { src = w1r; dh = g_w1r_h; dl = g_w1r_l; }
        else if ((j -= P1) < P1) { src = w1o; dh = g_w1o_h; dl = g_w1o_l; }
        else if ((j -= P1) < P2) { src = w2r; dh = g_w2_h; dl = g_w2_l; }
        else if ((j -= P2) < P2) { src = w2o; dh = g_w2_h + 2 * P2; dl = g_w2_l + 2 * P2; }
        else if ((j -= P2) < P3) { src = w3r; dh = g_w3r_h; dl = g_w3r_l; }
        else if ((j -= P3) < P3) { src = w3o; dh = g_w3o_h; dl = g_w3o_l; }
        else if ((j -= P3) < P4) { src = w4r; dh = g_w4_h; dl = g_w4_l; }
        else if ((j -= P4) < P4) { src = w4o; dh = g_w4_h + 2 * P4; dl = g_w4_l + 2 * P4; }
        else { j -= P4;            src = x; }
        int e = j * 2;
        float2 v = *reinterpret_cast<const float2*>(&src[e]);
        if (dh) {
            uint2 s = split2h(v.x, v.y);
            *reinterpret_cast<uint32_t*>(&dh[e]) = s.x;
            *reinterpret_cast<uint32_t*>(&dl[e]) = s.y;
        } else {
            *reinterpret_cast<uint32_t*>(&g_x16[e]) = pack2h(v.x, v.y);
        }
    }
}
// fp32 -> fp16 single convert
__global__ void cvt_kernel(const float* __restrict__ src, f16* __restrict__ dst, int n) {
    for (int e = (blockIdx.x * blockDim.x + threadIdx.x) * 2; e < n;
         e += gridDim.x * blockDim.x * 2) {
        float2 v = *reinterpret_cast<const float2*>(&src[e]);
        *reinterpret_cast<uint32_t*>(&dst[e]) = pack2h(v.x, v.y);
    }
}
// segment-sum over edges: 4 features per thread (R9-proven config)
template <int F>
__global__ void edge_agg_kernel(const float* __restrict__ feat, int featStride,
                                float* __restrict__ out, int outStride) {
    constexpr int V = F / 4;
    int idx = blockIdx.x * blockDim.x + threadIdx.x;
    int e = idx / V;
    int f = (idx % V) * 4;
    if (e >= NEDGES) return;
    int s = g_ei32[e];
    int d = g_ei32[NEDGES + e];
    float4 v = *reinterpret_cast<const float4*>(&feat[(size_t)s * featStride + f]);
    float* o = &out[(size_t)d * outStride + f];
    atomicAdd(o + 0, v.x); atomicAdd(o + 1, v.y);
    atomicAdd(o + 2, v.z); atomicAdd(o + 3, v.w);
}
// fused: h2 = relu(aggy + z2_root + b2); fp32 + fp16 single; pool (2 el/thread)
__global__ void combine_pool_kernel(const float* __restrict__ b2) {
    int idx = blockIdx.x * blockDim.x + threadIdx.x;
    if (idx >= NNODES * 64) return;
    int i = idx >> 6, f = (idx & 63) * 2;
    float2 ag = *reinterpret_cast<const float2*>(&g_aggy[i * D_ENC + f]);
    float2 zr = *reinterpret_cast<const float2*>(&g_z2[(size_t)i * 256 + 128 + f]);
    float2 bb = *reinterpret_cast<const float2*>(&b2[f]);
    float v0 = fmaxf(ag.x + zr.x + bb.x, 0.f);
    float v1 = fmaxf(ag.y + zr.y + bb.y, 0.f);
    *reinterpret_cast<float2*>(&g_h2f[i * D_ENC + f]) = make_float2(v0, v1);
    *reinterpret_cast<uint32_t*>(&g_h216[i * D_ENC + f]) = pack2h(v0, v1);
    int b = g_batch32[i];
    atomicAdd(&g_sums[b * D_ENC + f], v0);
    atomicAdd(&g_sums[b * D_ENC + f + 1], v1);
    if (f == 0) atomicAdd(&g_counts[b], 1.f);
}
__global__ void encoded_kernel(float* __restrict__ enc) {
    int idx = blockIdx.x * blockDim.x + threadIdx.x;
    if (idx >= NGRAPH * D_ENC) return;
    int g = idx >> 7;
    enc[idx] = g_sums[idx] / fmaxf(g_counts[g], 1.f);
}

// ---------------- pipelined mma.sync fp16 2-term GEMM ------------------------
// C[M,O] = sum_sides A_s[M,K] @ (Wh_s + Wl_s)[O,K]^T; A fp16 single, W hi/lo.
// block 128x128; 8 warps (4m x 2n); warp tile 32x64.
// K-chunk 32, 2-stage cp.async pipeline, ldmatrix.x4 fragment loads, 2 CTA/SM.
#define CHUNK 32
#define SROW  80
#define GTILE (128 * SROW)        // 10240
#define GSTAGE (3 * GTILE)        // 30720 (A, Wh, Wl)

template <bool DUAL_A, bool RELU, bool BIAS, bool F16OUT, bool OSPLIT>
__global__ void __launch_bounds__(256, 2) mmagemm(
    float* __restrict__ Cf, f16* __restrict__ C16,
    const f16* __restrict__ A1, const f16* __restrict__ A2,
    const f16* __restrict__ W1h, const f16* __restrict__ W1l,
    const f16* __restrict__ W2h, const f16* __restrict__ W2l,
    const float* __restrict__ bias, int M, int K, int O,
    float* __restrict__ C2, const float* __restrict__ bias2) {

    extern __shared__ char smraw[];
    const uint32_t smemBase = cvta_s(smraw);

    const int tid = threadIdx.x;
    const int wid = tid >> 5, lane = tid & 31;
    const int g = lane >> 2, t = lane & 3;
    const int warpM = (wid & 3) * 32, warpN = (wid >> 2) * 64;
    const int rowBase = blockIdx.y * 128, colBase = blockIdx.x * 128;

    const int laneRowA = (lane & 7) + ((lane & 8) ? 8 : 0);
    const int aK = (lane & 16) ? 16 : 0;
    const int laneRowW = (lane & 7) + ((lane & 16) ? 8 : 0);
    const int wK = (lane & 8) ? 16 : 0;
    uint32_t aoff[2], woff[4];
    #pragma unroll
    for (int mi = 0; mi < 2; ++mi)
        aoff[mi] = (uint32_t)((warpM + mi * 16 + laneRowA) * SROW + aK);
    #pragma unroll
    for (int p = 0; p < 4; ++p)
        woff[p] = (uint32_t)((warpN + p * 16 + laneRowW) * SROW + wK);

    float acc[2][8][4];
    #pragma unroll
    for (int a = 0; a < 2; ++a)
        #pragma unroll
        for (int b = 0; b < 8; ++b)
            #pragma unroll
            for (int c = 0; c < 4; ++c) acc[a][b][c] = 0.f;

    const int KC = (K + CHUNK - 1) / CHUNK;
    const int C = (DUAL_A ? 2 : 1) * KC;

    auto loadChunk = [&](int i, int stage) {
        int sIdx = DUAL_A ? (i / KC) : 0;
        int c = i - sIdx * KC;
        int k0 = c * CHUNK;
        const f16* A  = (DUAL_A && sIdx) ? A2  : A1;
        const f16* Wh = (DUAL_A && sIdx) ? W2h : W1h;
        const f16* Wl = (DUAL_A && sIdx) ? W2l : W1l;
        uint32_t sb = smemBase + stage * GSTAGE;
        #pragma unroll
        for (int j = 0; j < 6; ++j) {
            int idx = tid + j * 256;          // 0..1535
            int tile = idx >> 9;              // 0=A, 1=Wh, 2=Wl
            int r = (idx >> 2) & 127;
            int sg = idx & 3;
            int gk = k0 + sg * 8;
            const f16* src;
            int ok;
            if (tile == 0) {
                int gr = rowBase + r;
                ok = (gr < M) && (gk + 8 <= K);
                src = ok ? A + (size_t)gr * K + gk : A;
            } else {
                int gw = colBase + r;
                ok = (gw < O) && (gk + 8 <= K);
                const f16* base = (tile == 1) ? Wh : Wl;
                src = ok ? base + (size_t)gw * K + gk : base;
            }
            uint32_t dst = sb + tile * GTILE + (uint32_t)(r * SROW + sg * 16);
            int sz = ok ? 16 : 0;
            asm volatile("cp.async.cg.shared.global [%0], [%1], 16, %2;"
                         :: "r"(dst), "l"(src), "r"(sz) : "memory");
        }
        asm volatile("cp.async.commit_group;" ::: "memory");
    };

    auto computeChunk = [&](int stage) {
        uint32_t sb = smemBase + stage * GSTAGE;
        uint32_t bA = sb, bWh = sb + GTILE, bWl = sb + 2 * GTILE;
        #pragma unroll
        for (int ks = 0; ks < 2; ++ks) {
            uint32_t koff = ks * 32;
            uint32_t a[2][4];
            LDMX4(a[0], bA + aoff[0] + koff);
            LDMX4(a[1], bA + aoff[1] + koff);
            #pragma unroll
            for (int p = 0; p < 4; ++p) {
                uint32_t wh[4];
                LDMX4(wh, bWh + woff[p] + koff);
                mma16816(acc[0][2 * p],     a[0], wh[0], wh[1]);
                mma16816(acc[1][2 * p],     a[1], wh[0], wh[1]);
                mma16816(acc[0][2 * p + 1], a[0], wh[2], wh[3]);
                mma16816(acc[1][2 * p + 1], a[1], wh[2], wh[3]);
                uint32_t wl[4];
                LDMX4(wl, bWl + woff[p] + koff);
                mma16816(acc[0][2 * p],     a[0], wl[0], wl[1]);
                mma16816(acc[1][2 * p],     a[1], wl[0], wl[1]);
                mma16816(acc[0][2 * p + 1], a[0], wl[2], wl[3]);
                mma16816(acc[1][2 * p + 1], a[1], wl[2], wl[3]);
            }
        }
    };

    loadChunk(0, 0);
    for (int c = 0; c < C; ++c) {
        if (c + 1 < C) {
            loadChunk(c + 1, (c + 1) & 1);
            asm volatile("cp.async.wait_group 1;" ::: "memory");
        } else {
            asm volatile("cp.async.wait_group 0;" ::: "memory");
        }
        __syncthreads();
        computeChunk(c & 1);
        __syncthreads();
    }

    // ---- epilogue (cols always even; pair stores unconditional) ----
    #pragma unroll
    for (int mi = 0; mi < 2; ++mi) {
        #pragma unroll
        for (int half = 0; half < 2; ++half) {
            int row = rowBase + warpM + mi * 16 + g + half * 8;
            if (row >= M) continue;
            #pragma unroll
            for (int ni = 0; ni < 8; ++ni) {
                int col = colBase + warpN + ni * 8 + 2 * t;
                if (col >= O) continue;
                float v0 = acc[mi][ni][half * 2 + 0];
                float v1 = acc[mi][ni][half * 2 + 1];
                if (BIAS) {
                    float2 bb = *reinterpret_cast<const float2*>(&bias[col]);
                    v0 += bb.x; v1 += bb.y;
                }
                if (RELU) { v0 = fmaxf(v0, 0.f); v1 = fmaxf(v1, 0.f); }
                if (OSPLIT) {
                    // O==128: cols<64 -> Cf[row*64+col] (rel); cols>=64 -> C2 + bias2 (root)
                    if (col < 64) {
                        *reinterpret_cast<float2*>(&Cf[(size_t)row * 64 + col]) =
                            make_float2(v0, v1);
                    } else {
                        int c2 = col - 64;
                        float2 bb = *reinterpret_cast<const float2*>(&bias2[c2]);
                        *reinterpret_cast<float2*>(&C2[(size_t)row * 64 + c2]) =
                            make_float2(v0 + bb.x, v1 + bb.y);
                    }
                } else if (F16OUT) {
                    *reinterpret_cast<uint32_t*>(&C16[(size_t)row * O + col]) = pack2h(v0, v1);
                } else {
                    *reinterpret_cast<float2*>(&Cf[(size_t)row * O + col]) =
                        make_float2(v0, v1);
                }
            }
        }
    }
}

// ---------------- launch ----------------------------------------------------
extern "C" void kernel_launch(void* const* d_in, const int* in_sizes, int n_in,
                              void* d_out, int out_size) {
    const float* x         = (const float*)d_in[0];
    const int*   ei_raw    = (const int*)d_in[1];
    const int*   batch_raw = (const int*)d_in[2];
    const float* W1_rel = (const float*)d_in[3];
    const float* b1     = (const float*)d_in[4];
    const float* W1_root= (const float*)d_in[5];
    const float* W2_rel = (const float*)d_in[6];
    const float* b2     = (const float*)d_in[7];
    const float* W2_root= (const float*)d_in[8];
    const float* W3_rel = (const float*)d_in[9];
    const float* b3     = (const float*)d_in[10];
    const float* W3_root= (const float*)d_in[11];
    const float* W4_rel = (const float*)d_in[12];
    const float* b4     = (const float*)d_in[13];
    const float* W4_root= (const float*)d_in[14];

    float* out = (float*)d_out;
    float* enc = out + (size_t)NNODES * D_IN;

    float *aggx, *aggy, *h2f, *aggh2, *z2, *z4;
    f16 *x16, *aggx16, *h116, *h216, *ah216;
    f16 *w1r_h, *w1r_l, *w1o_h, *w1o_l, *w2_h, *w2_l, *w3r_h, *w3r_l, *w3o_h, *w3o_l, *w4_h, *w4_l;
    cudaGetSymbolAddress((void**)&aggx, g_aggx);   cudaGetSymbolAddress((void**)&aggy, g_aggy);
    cudaGetSymbolAddress((void**)&h2f, g_h2f);     cudaGetSymbolAddress((void**)&aggh2, g_aggh2);
    cudaGetSymbolAddress((void**)&z2, g_z2);       cudaGetSymbolAddress((void**)&z4, g_z4);
    cudaGetSymbolAddress((void**)&x16, g_x16);     cudaGetSymbolAddress((void**)&aggx16, g_aggx16);
    cudaGetSymbolAddress((void**)&h116, g_h116);   cudaGetSymbolAddress((void**)&h216, g_h216);
    cudaGetSymbolAddress((void**)&ah216, g_ah216);
    cudaGetSymbolAddress((void**)&w1r_h, g_w1r_h); cudaGetSymbolAddress((void**)&w1r_l, g_w1r_l);
    cudaGetSymbolAddress((void**)&w1o_h, g_w1o_h); cudaGetSymbolAddress((void**)&w1o_l, g_w1o_l);
    cudaGetSymbolAddress((void**)&w2_h, g_w2_h);   cudaGetSymbolAddress((void**)&w2_l, g_w2_l);
    cudaGetSymbolAddress((void**)&w3r_h, g_w3r_h); cudaGetSymbolAddress((void**)&w3r_l, g_w3r_l);
    cudaGetSymbolAddress((void**)&w3o_h, g_w3o_h); cudaGetSymbolAddress((void**)&w3o_l, g_w3o_l);
    cudaGetSymbolAddress((void**)&w4_h, g_w4_h);   cudaGetSymbolAddress((void**)&w4_l, g_w4_l);

    const int T = 256;
    const int MB = (NNODES + 127) / 128;   // 391
    constexpr int SMEM = 2 * GSTAGE;       // 61440

    cudaFuncSetAttribute(mmagemm<true,  true,  true,  true,  false>, cudaFuncAttributeMaxDynamicSharedMemorySize, SMEM);
    cudaFuncSetAttribute(mmagemm<false, false, false, false, false>, cudaFuncAttributeMaxDynamicSharedMemorySize, SMEM);
    cudaFuncSetAttribute(mmagemm<false, false, false, false, true >, cudaFuncAttributeMaxDynamicSharedMemorySize, SMEM);

    // ---- setup
    detect_kernel<<<1, 1>>>(ei_raw);
    convert_kernel<<<(2 * NEDGES + T - 1) / T, T>>>(ei_raw, batch_raw);
    zero_all_kernel<<<1024, T>>>();
    split_static_kernel<<<1024, T>>>(W1_rel, W1_root, W2_rel, W2_root,
                                     W3_rel, W3_root, W4_rel, W4_root, x);

    // ---- L1: agg(x) then dual-A MMA -> h1 (fp16, relu, bias)
    edge_agg_kernel<64><<<(NEDGES * 16 + T - 1) / T, T>>>(x, D_IN, aggx, D_IN);
    cvt_kernel<<<512, T>>>(aggx, aggx16, NNODES * D_IN);
    {
        dim3 grid((D_H + 127) / 128, MB);
        mmagemm<true, true, true, true, false><<<grid, T, SMEM>>>(
            nullptr, h116,
            aggx16, x16,
            w1r_h, w1r_l, w1o_h, w1o_l,
            b1, NNODES, D_IN, D_H, nullptr, nullptr);
    }

    // ---- L2: single-A MMA (K=1000, O=256 cat) -> z2 fp32
    {
        dim3 grid(2, MB);
        mmagemm<false, false, false, false, false><<<grid, T, SMEM>>>(
            z2, nullptr,
            h116, nullptr,
            w2_h, w2_l, nullptr, nullptr,
            nullptr, NNODES, D_H, 256, nullptr, nullptr);
    }
    edge_agg_kernel<128><<<(NEDGES * 32 + T - 1) / T, T>>>(z2, 256, aggy, D_ENC);
    combine_pool_kernel<<<(NNODES * 64 + T - 1) / T, T>>>(b2);
    encoded_kernel<<<(NGRAPH * D_ENC + T - 1) / T, T>>>(enc);

    // ---- L3: agg(h2) then dual-A MMA -> h3 (reuse h1 buffer)
    edge_agg_kernel<128><<<(NEDGES * 32 + T - 1) / T, T>>>(h2f, D_ENC, aggh2, D_ENC);
    cvt_kernel<<<512, T>>>(aggh2, ah216, NNODES * D_ENC);
    {
        dim3 grid((D_H + 127) / 128, MB);
        mmagemm<true, true, true, true, false><<<grid, T, SMEM>>>(
            nullptr, h116,
            ah216, h216,
            w3r_h, w3r_l, w3o_h, w3o_l,
            b3, NNODES, D_ENC, D_H, nullptr, nullptr);
    }

    // ---- L4: single-A MMA (K=1000, O=128 cat); rel half -> z4, root+b4 -> out
    {
        dim3 grid(1, MB);
        mmagemm<false, false, false, false, true><<<grid, T, SMEM>>>(
            z4, nullptr,
            h116, nullptr,
            w4_h, w4_l, nullptr, nullptr,
            nullptr, NNODES, D_H, 128, out, b4);
    }
    edge_agg_kernel<64><<<(NEDGES * 16 + T - 1) / T, T>>>(z4, 64, out, D_IN);
}

// round 13
// speedup vs baseline: 1.9771x; 1.3207x over previous
#include <cuda_runtime.h>
#include <cuda_fp16.h>
#include <cstdint>

#define NNODES 50000
#define NEDGES 200000
#define NGRAPH 2048
#define D_IN   64
#define D_H    1000
#define D_ENC  128

typedef __half f16;

// ---------------- scratch (static device allocations; no cudaMalloc) --------
__device__ float g_aggx [NNODES * D_IN];
__device__ float g_aggy [NNODES * D_ENC];
__device__ float g_h2f  [NNODES * D_ENC];
__device__ float g_aggh2[NNODES * D_ENC];
__device__ float g_z2   [NNODES * 256];   // cols 0..127 rel, 128..255 root
__device__ float g_z4   [NNODES * 64];    // z4 rel half only (root fused into out)
__device__ float g_sums [NGRAPH * D_ENC];
__device__ float g_counts[NGRAPH];
__device__ int   g_ei32[2 * NEDGES];
__device__ int   g_batch32[NNODES];
__device__ int   g_is64;

// fp16 operands (all single precision fp16)
__device__ __align__(16) f16 g_x16   [NNODES * D_IN];
__device__ __align__(16) f16 g_aggx16[NNODES * D_IN];
__device__ __align__(16) f16 g_h116  [(size_t)NNODES * D_H];
__device__ __align__(16) f16 g_h216  [NNODES * D_ENC];
__device__ __align__(16) f16 g_ah216 [NNODES * D_ENC];
__device__ __align__(16) f16 g_w1r16[D_H * D_IN];
__device__ __align__(16) f16 g_w1o16[D_H * D_IN];
__device__ __align__(16) f16 g_w216 [256 * D_H];
__device__ __align__(16) f16 g_w3r16[D_H * D_ENC];
__device__ __align__(16) f16 g_w3o16[D_H * D_ENC];
__device__ __align__(16) f16 g_w416 [128 * D_H];

// ---------------- helpers ----------------------------------------------------
__device__ __forceinline__ uint32_t pack2h(float v0, float v1) {
    uint32_t p;
    asm("cvt.rn.f16x2.f32 %0, %1, %2;" : "=r"(p) : "f"(v1), "f"(v0));
    return p;
}
__device__ __forceinline__ void mma16816(float* d, const uint32_t* a, uint32_t b0, uint32_t b1) {
    asm volatile(
        "mma.sync.aligned.m16n8k16.row.col.f32.f16.f16.f32 "
        "{%0,%1,%2,%3}, {%4,%5,%6,%7}, {%8,%9}, {%0,%1,%2,%3};"
        : "+f"(d[0]), "+f"(d[1]), "+f"(d[2]), "+f"(d[3])
        : "r"(a[0]), "r"(a[1]), "r"(a[2]), "r"(a[3]), "r"(b0), "r"(b1));
}
__device__ __forceinline__ uint32_t cvta_s(const void* p) {
    uint32_t a;
    asm("{ .reg .u64 t; cvta.to.shared.u64 t, %1; cvt.u32.u64 %0, t; }" : "=r"(a) : "l"(p));
    return a;
}
#define LDMX4(r, a) \
    asm volatile("ldmatrix.sync.aligned.m8n8.x4.shared.b16 {%0,%1,%2,%3}, [%4];" \
        : "=r"((r)[0]), "=r"((r)[1]), "=r"((r)[2]), "=r"((r)[3]) : "r"(a))

// ---------------- dtype detection + conversion ------------------------------
__global__ void detect_kernel(const int* __restrict__ ei_raw) {
    int odd_zero = 1;
    #pragma unroll
    for (int i = 0; i < 16; ++i)
        if (ei_raw[2 * i + 1] != 0) odd_zero = 0;
    g_is64 = odd_zero;
}
__global__ void convert_kernel(const int* __restrict__ ei_raw, const int* __restrict__ batch_raw) {
    int i = blockIdx.x * blockDim.x + threadIdx.x;
    int is64 = g_is64;
    if (i < 2 * NEDGES) g_ei32[i] = is64 ? ei_raw[2 * i] : ei_raw[i];
    if (i < NNODES)     g_batch32[i] = is64 ? batch_raw[2 * i] : batch_raw[i];
}

// ---------------- merged utility kernels -------------------------------------
__global__ void zero_all_kernel() {
    float4 z = make_float4(0.f, 0.f, 0.f, 0.f);
    float4* aggy  = reinterpret_cast<float4*>(g_aggy);
    float4* aggh2 = reinterpret_cast<float4*>(g_aggh2);
    float4* aggx  = reinterpret_cast<float4*>(g_aggx);
    float4* sums  = reinterpret_cast<float4*>(g_sums);
    float4* cnts  = reinterpret_cast<float4*>(g_counts);
    for (int i = blockIdx.x * blockDim.x + threadIdx.x; i < NNODES * D_ENC / 4;
         i += gridDim.x * blockDim.x) {
        aggy[i] = z;
        aggh2[i] = z;
        if (i < NNODES * D_IN / 4) aggx[i] = z;
        if (i < NGRAPH * D_ENC / 4) sums[i] = z;
        if (i < NGRAPH / 4) cnts[i] = z;
    }
}
// weights + x -> fp16 single. one launch, 2 elements/iteration.
__global__ void split_static_kernel(
    const float* __restrict__ w1r, const float* __restrict__ w1o,
    const float* __restrict__ w2r, const float* __restrict__ w2o,
    const float* __restrict__ w3r, const float* __restrict__ w3o,
    const float* __restrict__ w4r, const float* __restrict__ w4o,
    const float* __restrict__ x) {
    const int P1 = D_H * D_IN / 2;     // 32000
    const int P2 = 128 * D_H / 2;      // 64000
    const int P3 = D_H * D_ENC / 2;    // 64000
    const int P4 = 64 * D_H / 2;       // 32000
    const int PX = NNODES * D_IN / 2;  // 1600000
    const int TOTP = 2 * P1 + 2 * P2 + 2 * P3 + 2 * P4 + PX;
    for (int p = blockIdx.x * blockDim.x + threadIdx.x; p < TOTP;
         p += gridDim.x * blockDim.x) {
        const float* src; f16* dst; int j = p;
        if (j < P1)              { src = w1r; dst = g_w1r16; }
        else if ((j -= P1) < P1) { src = w1o; dst = g_w1o16; }
        else if ((j -= P1) < P2) { src = w2r; dst = g_w216; }
        else if ((j -= P2) < P2) { src = w2o; dst = g_w216 + 2 * P2; }
        else if ((j -= P2) < P3) { src = w3r; dst = g_w3r16; }
        else if ((j -= P3) < P3) { src = w3o; dst = g_w3o16; }
        else if ((j -= P3) < P4) { src = w4r; dst = g_w416; }
        else if ((j -= P4) < P4) { src = w4o; dst = g_w416 + 2 * P4; }
        else { j -= P4;            src = x;   dst = g_x16; }
        int e = j * 2;
        float2 v = *reinterpret_cast<const float2*>(&src[e]);
        *reinterpret_cast<uint32_t*>(&dst[e]) = pack2h(v.x, v.y);
    }
}
// fp32 -> fp16 single convert
__global__ void cvt_kernel(const float* __restrict__ src, f16* __restrict__ dst, int n) {
    for (int e = (blockIdx.x * blockDim.x + threadIdx.x) * 2; e < n;
         e += gridDim.x * blockDim.x * 2) {
        float2 v = *reinterpret_cast<const float2*>(&src[e]);
        *reinterpret_cast<uint32_t*>(&dst[e]) = pack2h(v.x, v.y);
    }
}
// segment-sum over edges: 4 features per thread (R9-proven config)
template <int F>
__global__ void edge_agg_kernel(const float* __restrict__ feat, int featStride,
                                float* __restrict__ out, int outStride) {
    constexpr int V = F / 4;
    int idx = blockIdx.x * blockDim.x + threadIdx.x;
    int e = idx / V;
    int f = (idx % V) * 4;
    if (e >= NEDGES) return;
    int s = g_ei32[e];
    int d = g_ei32[NEDGES + e];
    float4 v = *reinterpret_cast<const float4*>(&feat[(size_t)s * featStride + f]);
    float* o = &out[(size_t)d * outStride + f];
    atomicAdd(o + 0, v.x); atomicAdd(o + 1, v.y);
    atomicAdd(o + 2, v.z); atomicAdd(o + 3, v.w);
}
// fused: h2 = relu(aggy + z2_root + b2); fp32 + fp16 single; pool (2 el/thread)
__global__ void combine_pool_kernel(const float* __restrict__ b2) {
    int idx = blockIdx.x * blockDim.x + threadIdx.x;
    if (idx >= NNODES * 64) return;
    int i = idx >> 6, f = (idx & 63) * 2;
    float2 ag = *reinterpret_cast<const float2*>(&g_aggy[i * D_ENC + f]);
    float2 zr = *reinterpret_cast<const float2*>(&g_z2[(size_t)i * 256 + 128 + f]);
    float2 bb = *reinterpret_cast<const float2*>(&b2[f]);
    float v0 = fmaxf(ag.x + zr.x + bb.x, 0.f);
    float v1 = fmaxf(ag.y + zr.y + bb.y, 0.f);
    *reinterpret_cast<float2*>(&g_h2f[i * D_ENC + f]) = make_float2(v0, v1);
    *reinterpret_cast<uint32_t*>(&g_h216[i * D_ENC + f]) = pack2h(v0, v1);
    int b = g_batch32[i];
    atomicAdd(&g_sums[b * D_ENC + f], v0);
    atomicAdd(&g_sums[b * D_ENC + f + 1], v1);
    if (f == 0) atomicAdd(&g_counts[b], 1.f);
}
__global__ void encoded_kernel(float* __restrict__ enc) {
    int idx = blockIdx.x * blockDim.x + threadIdx.x;
    if (idx >= NGRAPH * D_ENC) return;
    int g = idx >> 7;
    enc[idx] = g_sums[idx] / fmaxf(g_counts[g], 1.f);
}

// ---------------- pipelined mma.sync fp16 single-pass GEMM -------------------
// C[M,O] = sum_sides A_s[M,K] @ W_s[O,K]^T; all operands single fp16.
// block 128x128; 8 warps (4m x 2n); warp tile 32x64.
// K-chunk 32, 2-stage cp.async pipeline, ldmatrix.x4 fragment loads, 2 CTA/SM.
#define CHUNK 32
#define SROW  80
#define GTILE (128 * SROW)        // 10240
#define GSTAGE (2 * GTILE)        // 20480 (A, W)

template <bool DUAL_A, bool RELU, bool BIAS, bool F16OUT, bool OSPLIT>
__global__ void __launch_bounds__(256, 2) mmagemm(
    float* __restrict__ Cf, f16* __restrict__ C16,
    const f16* __restrict__ A1, const f16* __restrict__ A2,
    const f16* __restrict__ W1, const f16* __restrict__ W2,
    const float* __restrict__ bias, int M, int K, int O,
    float* __restrict__ C2, const float* __restrict__ bias2) {

    extern __shared__ char smraw[];
    const uint32_t smemBase = cvta_s(smraw);

    const int tid = threadIdx.x;
    const int wid = tid >> 5, lane = tid & 31;
    const int g = lane >> 2, t = lane & 3;
    const int warpM = (wid & 3) * 32, warpN = (wid >> 2) * 64;
    const int rowBase = blockIdx.y * 128, colBase = blockIdx.x * 128;

    const int laneRowA = (lane & 7) + ((lane & 8) ? 8 : 0);
    const int aK = (lane & 16) ? 16 : 0;
    const int laneRowW = (lane & 7) + ((lane & 16) ? 8 : 0);
    const int wK = (lane & 8) ? 16 : 0;
    uint32_t aoff[2], woff[4];
    #pragma unroll
    for (int mi = 0; mi < 2; ++mi)
        aoff[mi] = (uint32_t)((warpM + mi * 16 + laneRowA) * SROW + aK);
    #pragma unroll
    for (int p = 0; p < 4; ++p)
        woff[p] = (uint32_t)((warpN + p * 16 + laneRowW) * SROW + wK);

    float acc[2][8][4];
    #pragma unroll
    for (int a = 0; a < 2; ++a)
        #pragma unroll
        for (int b = 0; b < 8; ++b)
            #pragma unroll
            for (int c = 0; c < 4; ++c) acc[a][b][c] = 0.f;

    const int KC = (K + CHUNK - 1) / CHUNK;
    const int C = (DUAL_A ? 2 : 1) * KC;

    auto loadChunk = [&](int i, int stage) {
        int sIdx = DUAL_A ? (i / KC) : 0;
        int c = i - sIdx * KC;
        int k0 = c * CHUNK;
        const f16* A = (DUAL_A && sIdx) ? A2 : A1;
        const f16* W = (DUAL_A && sIdx) ? W2 : W1;
        uint32_t sb = smemBase + stage * GSTAGE;
        #pragma unroll
        for (int j = 0; j < 4; ++j) {
            int idx = tid + j * 256;          // 0..1023
            int tile = idx >> 9;              // 0=A, 1=W
            int r = (idx >> 2) & 127;
            int sg = idx & 3;
            int gk = k0 + sg * 8;
            const f16* src;
            int ok;
            if (tile == 0) {
                int gr = rowBase + r;
                ok = (gr < M) && (gk + 8 <= K);
                src = ok ? A + (size_t)gr * K + gk : A;
            } else {
                int gw = colBase + r;
                ok = (gw < O) && (gk + 8 <= K);
                src = ok ? W + (size_t)gw * K + gk : W;
            }
            uint32_t dst = sb + tile * GTILE + (uint32_t)(r * SROW + sg * 16);
            int sz = ok ? 16 : 0;
            asm volatile("cp.async.cg.shared.global [%0], [%1], 16, %2;"
                         :: "r"(dst), "l"(src), "r"(sz) : "memory");
        }
        asm volatile("cp.async.commit_group;" ::: "memory");
    };

    auto computeChunk = [&](int stage) {
        uint32_t sb = smemBase + stage * GSTAGE;
        uint32_t bA = sb, bW = sb + GTILE;
        #pragma unroll
        for (int ks = 0; ks < 2; ++ks) {
            uint32_t koff = ks * 32;
            uint32_t a[2][4];
            LDMX4(a[0], bA + aoff[0] + koff);
            LDMX4(a[1], bA + aoff[1] + koff);
            #pragma unroll
            for (int p = 0; p < 4; ++p) {
                uint32_t w[4];
                LDMX4(w, bW + woff[p] + koff);
                mma16816(acc[0][2 * p],     a[0], w[0], w[1]);
                mma16816(acc[1][2 * p],     a[1], w[0], w[1]);
                mma16816(acc[0][2 * p + 1], a[0], w[2], w[3]);
                mma16816(acc[1][2 * p + 1], a[1], w[2], w[3]);
            }
        }
    };

    loadChunk(0, 0);
    for (int c = 0; c < C; ++c) {
        if (c + 1 < C) {
            loadChunk(c + 1, (c + 1) & 1);
            asm volatile("cp.async.wait_group 1;" ::: "memory");
        } else {
            asm volatile("cp.async.wait_group 0;" ::: "memory");
        }
        __syncthreads();
        computeChunk(c & 1);
        __syncthreads();
    }

    // ---- epilogue (cols always even; pair stores unconditional) ----
    #pragma unroll
    for (int mi = 0; mi < 2; ++mi) {
        #pragma unroll
        for (int half = 0; half < 2; ++half) {
            int row = rowBase + warpM + mi * 16 + g + half * 8;
            if (row >= M) continue;
            #pragma unroll
            for (int ni = 0; ni < 8; ++ni) {
                int col = colBase + warpN + ni * 8 + 2 * t;
                if (col >= O) continue;
                float v0 = acc[mi][ni][half * 2 + 0];
                float v1 = acc[mi][ni][half * 2 + 1];
                if (BIAS) {
                    float2 bb = *reinterpret_cast<const float2*>(&bias[col]);
                    v0 += bb.x; v1 += bb.y;
                }
                if (RELU) { v0 = fmaxf(v0, 0.f); v1 = fmaxf(v1, 0.f); }
                if (OSPLIT) {
                    // O==128: cols<64 -> Cf[row*64+col] (rel); cols>=64 -> C2 + bias2 (root)
                    if (col < 64) {
                        *reinterpret_cast<float2*>(&Cf[(size_t)row * 64 + col]) =
                            make_float2(v0, v1);
                    } else {
                        int c2 = col - 64;
                        float2 bb = *reinterpret_cast<const float2*>(&bias2[c2]);
                        *reinterpret_cast<float2*>(&C2[(size_t)row * 64 + c2]) =
                            make_float2(v0 + bb.x, v1 + bb.y);
                    }
                } else if (F16OUT) {
                    *reinterpret_cast<uint32_t*>(&C16[(size_t)row * O + col]) = pack2h(v0, v1);
                } else {
                    *reinterpret_cast<float2*>(&Cf[(size_t)row * O + col]) =
                        make_float2(v0, v1);
                }
            }
        }
    }
}

// ---------------- launch ----------------------------------------------------
extern "C" void kernel_launch(void* const* d_in, const int* in_sizes, int n_in,
                              void* d_out, int out_size) {
    const float* x         = (const float*)d_in[0];
    const int*   ei_raw    = (const int*)d_in[1];
    const int*   batch_raw = (const int*)d_in[2];
    const float* W1_rel = (const float*)d_in[3];
    const float* b1     = (const float*)d_in[4];
    const float* W1_root= (const float*)d_in[5];
    const float* W2_rel = (const float*)d_in[6];
    const float* b2     = (const float*)d_in[7];
    const float* W2_root= (const float*)d_in[8];
    const float* W3_rel = (const float*)d_in[9];
    const float* b3     = (const float*)d_in[10];
    const float* W3_root= (const float*)d_in[11];
    const float* W4_rel = (const float*)d_in[12];
    const float* b4     = (const float*)d_in[13];
    const float* W4_root= (const float*)d_in[14];

    float* out = (float*)d_out;
    float* enc = out + (size_t)NNODES * D_IN;

    float *aggx, *aggy, *h2f, *aggh2, *z2, *z4;
    f16 *x16, *aggx16, *h116, *h216, *ah216;
    f16 *w1r16, *w1o16, *w216, *w3r16, *w3o16, *w416;
    cudaGetSymbolAddress((void**)&aggx, g_aggx);   cudaGetSymbolAddress((void**)&aggy, g_aggy);
    cudaGetSymbolAddress((void**)&h2f, g_h2f);     cudaGetSymbolAddress((void**)&aggh2, g_aggh2);
    cudaGetSymbolAddress((void**)&z2, g_z2);       cudaGetSymbolAddress((void**)&z4, g_z4);
    cudaGetSymbolAddress((void**)&x16, g_x16);     cudaGetSymbolAddress((void**)&aggx16, g_aggx16);
    cudaGetSymbolAddress((void**)&h116, g_h116);   cudaGetSymbolAddress((void**)&h216, g_h216);
    cudaGetSymbolAddress((void**)&ah216, g_ah216);
    cudaGetSymbolAddress((void**)&w1r16, g_w1r16); cudaGetSymbolAddress((void**)&w1o16, g_w1o16);
    cudaGetSymbolAddress((void**)&w216, g_w216);
    cudaGetSymbolAddress((void**)&w3r16, g_w3r16); cudaGetSymbolAddress((void**)&w3o16, g_w3o16);
    cudaGetSymbolAddress((void**)&w416, g_w416);

    const int T = 256;
    const int MB = (NNODES + 127) / 128;   // 391
    constexpr int SMEM = 2 * GSTAGE;       // 40960

    cudaFuncSetAttribute(mmagemm<true,  true,  true,  true,  false>, cudaFuncAttributeMaxDynamicSharedMemorySize, SMEM);
    cudaFuncSetAttribute(mmagemm<false, false, false, false, false>, cudaFuncAttributeMaxDynamicSharedMemorySize, SMEM);
    cudaFuncSetAttribute(mmagemm<false, false, false, false, true >, cudaFuncAttributeMaxDynamicSharedMemorySize, SMEM);

    // ---- setup
    detect_kernel<<<1, 1>>>(ei_raw);
    convert_kernel<<<(2 * NEDGES + T - 1) / T, T>>>(ei_raw, batch_raw);
    zero_all_kernel<<<1024, T>>>();
    split_static_kernel<<<1024, T>>>(W1_rel, W1_root, W2_rel, W2_root,
                                     W3_rel, W3_root, W4_rel, W4_root, x);

    // ---- L1: agg(x) then dual-A MMA -> h1 (fp16, relu, bias)
    edge_agg_kernel<64><<<(NEDGES * 16 + T - 1) / T, T>>>(x, D_IN, aggx, D_IN);
    cvt_kernel<<<512, T>>>(aggx, aggx16, NNODES * D_IN);
    {
        dim3 grid((D_H + 127) / 128, MB);
        mmagemm<true, true, true, true, false><<<grid, T, SMEM>>>(
            nullptr, h116,
            aggx16, x16,
            w1r16, w1o16,
            b1, NNODES, D_IN, D_H, nullptr, nullptr);
    }

    // ---- L2: single-A MMA (K=1000, O=256 cat) -> z2 fp32
    {
        dim3 grid(2, MB);
        mmagemm<false, false, false, false, false><<<grid, T, SMEM>>>(
            z2, nullptr,
            h116, nullptr,
            w216, nullptr,
            nullptr, NNODES, D_H, 256, nullptr, nullptr);
    }
    edge_agg_kernel<128><<<(NEDGES * 32 + T - 1) / T, T>>>(z2, 256, aggy, D_ENC);
    combine_pool_kernel<<<(NNODES * 64 + T - 1) / T, T>>>(b2);
    encoded_kernel<<<(NGRAPH * D_ENC + T - 1) / T, T>>>(enc);

    // ---- L3: agg(h2) then dual-A MMA -> h3 (reuse h1 buffer)
    edge_agg_kernel<128><<<(NEDGES * 32 + T - 1) / T, T>>>(h2f, D_ENC, aggh2, D_ENC);
    cvt_kernel<<<512, T>>>(aggh2, ah216, NNODES * D_ENC);
    {
        dim3 grid((D_H + 127) / 128, MB);
        mmagemm<true, true, true, true, false><<<grid, T, SMEM>>>(
            nullptr, h116,
            ah216, h216,
            w3r16, w3o16,
            b3, NNODES, D_ENC, D_H, nullptr, nullptr);
    }

    // ---- L4: single-A MMA (K=1000, O=128 cat); rel half -> z4, root+b4 -> out
    {
        dim3 grid(1, MB);
        mmagemm<false, false, false, false, true><<<grid, T, SMEM>>>(
            z4, nullptr,
            h116, nullptr,
            w416, nullptr,
            nullptr, NNODES, D_H, 128, out, b4);
    }
    edge_agg_kernel<64><<<(NEDGES * 16 + T - 1) / T, T>>>(z4, 64, out, D_IN);
}

// round 14
// speedup vs baseline: 2.3896x; 1.2086x over previous
#include <cuda_runtime.h>
#include <cuda_fp16.h>
#include <cstdint>

#define NNODES 50000
#define NEDGES 200000
#define NGRAPH 2048
#define D_IN   64
#define D_H    1000
#define D_ENC  128

typedef __half f16;

// ---------------- scratch (static device allocations; no cudaMalloc) --------
__device__ float g_aggx [NNODES * D_IN];
__device__ float g_aggy [NNODES * D_ENC];
__device__ float g_h2f  [NNODES * D_ENC];
__device__ float g_aggh2[NNODES * D_ENC];
__device__ float g_z2   [NNODES * 256];   // cols 0..127 rel, 128..255 root
__device__ float g_z4   [NNODES * 64];    // z4 rel half only (root fused into out)
__device__ float g_sums [NGRAPH * D_ENC];
__device__ float g_counts[NGRAPH];
__device__ int   g_ei32[2 * NEDGES];
__device__ int   g_batch32[NNODES];
__device__ int   g_is64;

// fp16 operands (all single precision fp16)
__device__ __align__(16) f16 g_x16   [NNODES * D_IN];
__device__ __align__(16) f16 g_aggx16[NNODES * D_IN];
__device__ __align__(16) f16 g_h116  [(size_t)NNODES * D_H];
__device__ __align__(16) f16 g_h216  [NNODES * D_ENC];
__device__ __align__(16) f16 g_ah216 [NNODES * D_ENC];
__device__ __align__(16) f16 g_w1r16[D_H * D_IN];
__device__ __align__(16) f16 g_w1o16[D_H * D_IN];
__device__ __align__(16) f16 g_w216 [256 * D_H];
__device__ __align__(16) f16 g_w3r16[D_H * D_ENC];
__device__ __align__(16) f16 g_w3o16[D_H * D_ENC];
__device__ __align__(16) f16 g_w416 [128 * D_H];

// ---------------- helpers ----------------------------------------------------
__device__ __forceinline__ uint32_t pack2h(float v0, float v1) {
    uint32_t p;
    asm("cvt.rn.f16x2.f32 %0, %1, %2;" : "=r"(p) : "f"(v1), "f"(v0));
    return p;
}
__device__ __forceinline__ void red4(float* addr, float4 v) {
    asm volatile("red.global.add.v4.f32 [%0], {%1,%2,%3,%4};"
                 :: "l"(addr), "f"(v.x), "f"(v.y), "f"(v.z), "f"(v.w) : "memory");
}
__device__ __forceinline__ void red2(float* addr, float v0, float v1) {
    asm volatile("red.global.add.v2.f32 [%0], {%1,%2};"
                 :: "l"(addr), "f"(v0), "f"(v1) : "memory");
}
__device__ __forceinline__ void mma16816(float* d, const uint32_t* a, uint32_t b0, uint32_t b1) {
    asm volatile(
        "mma.sync.aligned.m16n8k16.row.col.f32.f16.f16.f32 "
        "{%0,%1,%2,%3}, {%4,%5,%6,%7}, {%8,%9}, {%0,%1,%2,%3};"
        : "+f"(d[0]), "+f"(d[1]), "+f"(d[2]), "+f"(d[3])
        : "r"(a[0]), "r"(a[1]), "r"(a[2]), "r"(a[3]), "r"(b0), "r"(b1));
}
__device__ __forceinline__ uint32_t cvta_s(const void* p) {
    uint32_t a;
    asm("{ .reg .u64 t; cvta.to.shared.u64 t, %1; cvt.u32.u64 %0, t; }" : "=r"(a) : "l"(p));
    return a;
}
#define LDMX4(r, a) \
    asm volatile("ldmatrix.sync.aligned.m8n8.x4.shared.b16 {%0,%1,%2,%3}, [%4];" \
        : "=r"((r)[0]), "=r"((r)[1]), "=r"((r)[2]), "=r"((r)[3]) : "r"(a))

// ---------------- dtype detection + conversion ------------------------------
__global__ void detect_kernel(const int* __restrict__ ei_raw) {
    int odd_zero = 1;
    #pragma unroll
    for (int i = 0; i < 16; ++i)
        if (ei_raw[2 * i + 1] != 0) odd_zero = 0;
    g_is64 = odd_zero;
}
__global__ void convert_kernel(const int* __restrict__ ei_raw, const int* __restrict__ batch_raw) {
    int i = blockIdx.x * blockDim.x + threadIdx.x;
    int is64 = g_is64;
    if (i < 2 * NEDGES) g_ei32[i] = is64 ? ei_raw[2 * i] : ei_raw[i];
    if (i < NNODES)     g_batch32[i] = is64 ? batch_raw[2 * i] : batch_raw[i];
}

// ---------------- merged utility kernels -------------------------------------
__global__ void zero_all_kernel() {
    float4 z = make_float4(0.f, 0.f, 0.f, 0.f);
    float4* aggy  = reinterpret_cast<float4*>(g_aggy);
    float4* aggh2 = reinterpret_cast<float4*>(g_aggh2);
    float4* aggx  = reinterpret_cast<float4*>(g_aggx);
    float4* sums  = reinterpret_cast<float4*>(g_sums);
    float4* cnts  = reinterpret_cast<float4*>(g_counts);
    for (int i = blockIdx.x * blockDim.x + threadIdx.x; i < NNODES * D_ENC / 4;
         i += gridDim.x * blockDim.x) {
        aggy[i] = z;
        aggh2[i] = z;
        if (i < NNODES * D_IN / 4) aggx[i] = z;
        if (i < NGRAPH * D_ENC / 4) sums[i] = z;
        if (i < NGRAPH / 4) cnts[i] = z;
    }
}
// weights + x -> fp16 single. one launch, 2 elements/iteration.
__global__ void split_static_kernel(
    const float* __restrict__ w1r, const float* __restrict__ w1o,
    const float* __restrict__ w2r, const float* __restrict__ w2o,
    const float* __restrict__ w3r, const float* __restrict__ w3o,
    const float* __restrict__ w4r, const float* __restrict__ w4o,
    const float* __restrict__ x) {
    const int P1 = D_H * D_IN / 2;     // 32000
    const int P2 = 128 * D_H / 2;      // 64000
    const int P3 = D_H * D_ENC / 2;    // 64000
    const int P4 = 64 * D_H / 2;       // 32000
    const int PX = NNODES * D_IN / 2;  // 1600000
    const int TOTP = 2 * P1 + 2 * P2 + 2 * P3 + 2 * P4 + PX;
    for (int p = blockIdx.x * blockDim.x + threadIdx.x; p < TOTP;
         p += gridDim.x * blockDim.x) {
        const float* src; f16* dst; int j = p;
        if (j < P1)              { src = w1r; dst = g_w1r16; }
        else if ((j -= P1) < P1) { src = w1o; dst = g_w1o16; }
        else if ((j -= P1) < P2) { src = w2r; dst = g_w216; }
        else if ((j -= P2) < P2) { src = w2o; dst = g_w216 + 2 * P2; }
        else if ((j -= P2) < P3) { src = w3r; dst = g_w3r16; }
        else if ((j -= P3) < P3) { src = w3o; dst = g_w3o16; }
        else if ((j -= P3) < P4) { src = w4r; dst = g_w416; }
        else if ((j -= P4) < P4) { src = w4o; dst = g_w416 + 2 * P4; }
        else { j -= P4;            src = x;   dst = g_x16; }
        int e = j * 2;
        float2 v = *reinterpret_cast<const float2*>(&src[e]);
        *reinterpret_cast<uint32_t*>(&dst[e]) = pack2h(v.x, v.y);
    }
}
// fp32 -> fp16 single convert
__global__ void cvt_kernel(const float* __restrict__ src, f16* __restrict__ dst, int n) {
    for (int e = (blockIdx.x * blockDim.x + threadIdx.x) * 2; e < n;
         e += gridDim.x * blockDim.x * 2) {
        float2 v = *reinterpret_cast<const float2*>(&src[e]);
        *reinterpret_cast<uint32_t*>(&dst[e]) = pack2h(v.x, v.y);
    }
}
// segment-sum over edges: 4 features per thread, vector RED (1 transaction)
template <int F>
__global__ void edge_agg_kernel(const float* __restrict__ feat, int featStride,
                                float* __restrict__ out, int outStride) {
    constexpr int V = F / 4;
    int idx = blockIdx.x * blockDim.x + threadIdx.x;
    int e = idx / V;
    int f = (idx % V) * 4;
    if (e >= NEDGES) return;
    int s = g_ei32[e];
    int d = g_ei32[NEDGES + e];
    float4 v = *reinterpret_cast<const float4*>(&feat[(size_t)s * featStride + f]);
    red4(&out[(size_t)d * outStride + f], v);
}
// fused: h2 = relu(aggy + z2_root + b2); fp32 + fp16 single; pool (2 el/thread)
__global__ void combine_pool_kernel(const float* __restrict__ b2) {
    int idx = blockIdx.x * blockDim.x + threadIdx.x;
    if (idx >= NNODES * 64) return;
    int i = idx >> 6, f = (idx & 63) * 2;
    float2 ag = *reinterpret_cast<const float2*>(&g_aggy[i * D_ENC + f]);
    float2 zr = *reinterpret_cast<const float2*>(&g_z2[(size_t)i * 256 + 128 + f]);
    float2 bb = *reinterpret_cast<const float2*>(&b2[f]);
    float v0 = fmaxf(ag.x + zr.x + bb.x, 0.f);
    float v1 = fmaxf(ag.y + zr.y + bb.y, 0.f);
    *reinterpret_cast<float2*>(&g_h2f[i * D_ENC + f]) = make_float2(v0, v1);
    *reinterpret_cast<uint32_t*>(&g_h216[i * D_ENC + f]) = pack2h(v0, v1);
    int b = g_batch32[i];
    red2(&g_sums[b * D_ENC + f], v0, v1);
    if (f == 0) atomicAdd(&g_counts[b], 1.f);
}
__global__ void encoded_kernel(float* __restrict__ enc) {
    int idx = blockIdx.x * blockDim.x + threadIdx.x;
    if (idx >= NGRAPH * D_ENC) return;
    int g = idx >> 7;
    enc[idx] = g_sums[idx] / fmaxf(g_counts[g], 1.f);
}

// ---------------- pipelined mma.sync fp16 single-pass GEMM -------------------
// C[M,O] = sum_sides A_s[M,K] @ W_s[O,K]^T; all operands single fp16.
// block 128x128; 8 warps (4m x 2n); warp tile 32x64.
// K-chunk 32, 2-stage cp.async pipeline, ldmatrix.x4 fragment loads, 2 CTA/SM.
#define CHUNK 32
#define SROW  80
#define GTILE (128 * SROW)        // 10240
#define GSTAGE (2 * GTILE)        // 20480 (A, W)

template <bool DUAL_A, bool RELU, bool BIAS, bool F16OUT, bool OSPLIT>
__global__ void __launch_bounds__(256, 2) mmagemm(
    float* __restrict__ Cf, f16* __restrict__ C16,
    const f16* __restrict__ A1, const f16* __restrict__ A2,
    const f16* __restrict__ W1, const f16* __restrict__ W2,
    const float* __restrict__ bias, int M, int K, int O,
    float* __restrict__ C2, const float* __restrict__ bias2) {

    extern __shared__ char smraw[];
    const uint32_t smemBase = cvta_s(smraw);

    const int tid = threadIdx.x;
    const int wid = tid >> 5, lane = tid & 31;
    const int g = lane >> 2, t = lane & 3;
    const int warpM = (wid & 3) * 32, warpN = (wid >> 2) * 64;
    const int rowBase = blockIdx.y * 128, colBase = blockIdx.x * 128;

    const int laneRowA = (lane & 7) + ((lane & 8) ? 8 : 0);
    const int aK = (lane & 16) ? 16 : 0;
    const int laneRowW = (lane & 7) + ((lane & 16) ? 8 : 0);
    const int wK = (lane & 8) ? 16 : 0;
    uint32_t aoff[2], woff[4];
    #pragma unroll
    for (int mi = 0; mi < 2; ++mi)
        aoff[mi] = (uint32_t)((warpM + mi * 16 + laneRowA) * SROW + aK);
    #pragma unroll
    for (int p = 0; p < 4; ++p)
        woff[p] = (uint32_t)((warpN + p * 16 + laneRowW) * SROW + wK);

    float acc[2][8][4];
    #pragma unroll
    for (int a = 0; a < 2; ++a)
        #pragma unroll
        for (int b = 0; b < 8; ++b)
            #pragma unroll
            for (int c = 0; c < 4; ++c) acc[a][b][c] = 0.f;

    const int KC = (K + CHUNK - 1) / CHUNK;
    const int C = (DUAL_A ? 2 : 1) * KC;

    auto loadChunk = [&](int i, int stage) {
        int sIdx = DUAL_A ? (i / KC) : 0;
        int c = i - sIdx * KC;
        int k0 = c * CHUNK;
        const f16* A = (DUAL_A && sIdx) ? A2 : A1;
        const f16* W = (DUAL_A && sIdx) ? W2 : W1;
        uint32_t sb = smemBase + stage * GSTAGE;
        #pragma unroll
        for (int j = 0; j < 4; ++j) {
            int idx = tid + j * 256;          // 0..1023
            int tile = idx >> 9;              // 0=A, 1=W
            int r = (idx >> 2) & 127;
            int sg = idx & 3;
            int gk = k0 + sg * 8;
            const f16* src;
            int ok;
            if (tile == 0) {
                int gr = rowBase + r;
                ok = (gr < M) && (gk + 8 <= K);
                src = ok ? A + (size_t)gr * K + gk : A;
            } else {
                int gw = colBase + r;
                ok = (gw < O) && (gk + 8 <= K);
                src = ok ? W + (size_t)gw * K + gk : W;
            }
            uint32_t dst = sb + tile * GTILE + (uint32_t)(r * SROW + sg * 16);
            int sz = ok ? 16 : 0;
            asm volatile("cp.async.cg.shared.global [%0], [%1], 16, %2;"
                         :: "r"(dst), "l"(src), "r"(sz) : "memory");
        }
        asm volatile("cp.async.commit_group;" ::: "memory");
    };

    auto computeChunk = [&](int stage) {
        uint32_t sb = smemBase + stage * GSTAGE;
        uint32_t bA = sb, bW = sb + GTILE;
        #pragma unroll
        for (int ks = 0; ks < 2; ++ks) {
            uint32_t koff = ks * 32;
            uint32_t a[2][4];
            LDMX4(a[0], bA + aoff[0] + koff);
            LDMX4(a[1], bA + aoff[1] + koff);
            #pragma unroll
            for (int p = 0; p < 4; ++p) {
                uint32_t w[4];
                LDMX4(w, bW + woff[p] + koff);
                mma16816(acc[0][2 * p],     a[0], w[0], w[1]);
                mma16816(acc[1][2 * p],     a[1], w[0], w[1]);
                mma16816(acc[0][2 * p + 1], a[0], w[2], w[3]);
                mma16816(acc[1][2 * p + 1], a[1], w[2], w[3]);
            }
        }
    };

    loadChunk(0, 0);
    for (int c = 0; c < C; ++c) {
        if (c + 1 < C) {
            loadChunk(c + 1, (c + 1) & 1);
            asm volatile("cp.async.wait_group 1;" ::: "memory");
        } else {
            asm volatile("cp.async.wait_group 0;" ::: "memory");
        }
        __syncthreads();
        computeChunk(c & 1);
        __syncthreads();
    }

    // ---- epilogue (cols always even; pair stores unconditional) ----
    #pragma unroll
    for (int mi = 0; mi < 2; ++mi) {
        #pragma unroll
        for (int half = 0; half < 2; ++half) {
            int row = rowBase + warpM + mi * 16 + g + half * 8;
            if (row >= M) continue;
            #pragma unroll
            for (int ni = 0; ni < 8; ++ni) {
                int col = colBase + warpN + ni * 8 + 2 * t;
                if (col >= O) continue;
                float v0 = acc[mi][ni][half * 2 + 0];
                float v1 = acc[mi][ni][half * 2 + 1];
                if (BIAS) {
                    float2 bb = *reinterpret_cast<const float2*>(&bias[col]);
                    v0 += bb.x; v1 += bb.y;
                }
                if (RELU) { v0 = fmaxf(v0, 0.f); v1 = fmaxf(v1, 0.f); }
                if (OSPLIT) {
                    // O==128: cols<64 -> Cf[row*64+col] (rel); cols>=64 -> C2 + bias2 (root)
                    if (col < 64) {
                        *reinterpret_cast<float2*>(&Cf[(size_t)row * 64 + col]) =
                            make_float2(v0, v1);
                    } else {
                        int c2 = col - 64;
                        float2 bb = *reinterpret_cast<const float2*>(&bias2[c2]);
                        *reinterpret_cast<float2*>(&C2[(size_t)row * 64 + c2]) =
                            make_float2(v0 + bb.x, v1 + bb.y);
                    }
                } else if (F16OUT) {
                    *reinterpret_cast<uint32_t*>(&C16[(size_t)row * O + col]) = pack2h(v0, v1);
                } else {
                    *reinterpret_cast<float2*>(&Cf[(size_t)row * O + col]) =
                        make_float2(v0, v1);
                }
            }
        }
    }
}

// ---------------- launch ----------------------------------------------------
extern "C" void kernel_launch(void* const* d_in, const int* in_sizes, int n_in,
                              void* d_out, int out_size) {
    const float* x         = (const float*)d_in[0];
    const int*   ei_raw    = (const int*)d_in[1];
    const int*   batch_raw = (const int*)d_in[2];
    const float* W1_rel = (const float*)d_in[3];
    const float* b1     = (const float*)d_in[4];
    const float* W1_root= (const float*)d_in[5];
    const float* W2_rel = (const float*)d_in[6];
    const float* b2     = (const float*)d_in[7];
    const float* W2_root= (const float*)d_in[8];
    const float* W3_rel = (const float*)d_in[9];
    const float* b3     = (const float*)d_in[10];
    const float* W3_root= (const float*)d_in[11];
    const float* W4_rel = (const float*)d_in[12];
    const float* b4     = (const float*)d_in[13];
    const float* W4_root= (const float*)d_in[14];

    float* out = (float*)d_out;
    float* enc = out + (size_t)NNODES * D_IN;

    float *aggx, *aggy, *h2f, *aggh2, *z2, *z4;
    f16 *x16, *aggx16, *h116, *h216, *ah216;
    f16 *w1r16, *w1o16, *w216, *w3r16, *w3o16, *w416;
    cudaGetSymbolAddress((void**)&aggx, g_aggx);   cudaGetSymbolAddress((void**)&aggy, g_aggy);
    cudaGetSymbolAddress((void**)&h2f, g_h2f);     cudaGetSymbolAddress((void**)&aggh2, g_aggh2);
    cudaGetSymbolAddress((void**)&z2, g_z2);       cudaGetSymbolAddress((void**)&z4, g_z4);
    cudaGetSymbolAddress((void**)&x16, g_x16);     cudaGetSymbolAddress((void**)&aggx16, g_aggx16);
    cudaGetSymbolAddress((void**)&h116, g_h116);   cudaGetSymbolAddress((void**)&h216, g_h216);
    cudaGetSymbolAddress((void**)&ah216, g_ah216);
    cudaGetSymbolAddress((void**)&w1r16, g_w1r16); cudaGetSymbolAddress((void**)&w1o16, g_w1o16);
    cudaGetSymbolAddress((void**)&w216, g_w216);
    cudaGetSymbolAddress((void**)&w3r16, g_w3r16); cudaGetSymbolAddress((void**)&w3o16, g_w3o16);
    cudaGetSymbolAddress((void**)&w416, g_w416);

    const int T = 256;
    const int MB = (NNODES + 127) / 128;   // 391
    constexpr int SMEM = 2 * GSTAGE;       // 40960

    cudaFuncSetAttribute(mmagemm<true,  true,  true,  true,  false>, cudaFuncAttributeMaxDynamicSharedMemorySize, SMEM);
    cudaFuncSetAttribute(mmagemm<false, false, false, false, false>, cudaFuncAttributeMaxDynamicSharedMemorySize, SMEM);
    cudaFuncSetAttribute(mmagemm<false, false, false, false, true >, cudaFuncAttributeMaxDynamicSharedMemorySize, SMEM);

    // ---- setup
    detect_kernel<<<1, 1>>>(ei_raw);
    convert_kernel<<<(2 * NEDGES + T - 1) / T, T>>>(ei_raw, batch_raw);
    zero_all_kernel<<<1024, T>>>();
    split_static_kernel<<<1024, T>>>(W1_rel, W1_root, W2_rel, W2_root,
                                     W3_rel, W3_root, W4_rel, W4_root, x);

    // ---- L1: agg(x) then dual-A MMA -> h1 (fp16, relu, bias)
    edge_agg_kernel<64><<<(NEDGES * 16 + T - 1) / T, T>>>(x, D_IN, aggx, D_IN);
    cvt_kernel<<<512, T>>>(aggx, aggx16, NNODES * D_IN);
    {
        dim3 grid((D_H + 127) / 128, MB);
        mmagemm<true, true, true, true, false><<<grid, T, SMEM>>>(
            nullptr, h116,
            aggx16, x16,
            w1r16, w1o16,
            b1, NNODES, D_IN, D_H, nullptr, nullptr);
    }

    // ---- L2: single-A MMA (K=1000, O=256 cat) -> z2 fp32
    {
        dim3 grid(2, MB);
        mmagemm<false, false, false, false, false><<<grid, T, SMEM>>>(
            z2, nullptr,
            h116, nullptr,
            w216, nullptr,
            nullptr, NNODES, D_H, 256, nullptr, nullptr);
    }
    edge_agg_kernel<128><<<(NEDGES * 32 + T - 1) / T, T>>>(z2, 256, aggy, D_ENC);
    combine_pool_kernel<<<(NNODES * 64 + T - 1) / T, T>>>(b2);
    encoded_kernel<<<(NGRAPH * D_ENC + T - 1) / T, T>>>(enc);

    // ---- L3: agg(h2) then dual-A MMA -> h3 (reuse h1 buffer)
    edge_agg_kernel<128><<<(NEDGES * 32 + T - 1) / T, T>>>(h2f, D_ENC, aggh2, D_ENC);
    cvt_kernel<<<512, T>>>(aggh2, ah216, NNODES * D_ENC);
    {
        dim3 grid((D_H + 127) / 128, MB);
        mmagemm<true, true, true, true, false><<<grid, T, SMEM>>>(
            nullptr, h116,
            ah216, h216,
            w3r16, w3o16,
            b3, NNODES, D_ENC, D_H, nullptr, nullptr);
    }

    // ---- L4: single-A MMA (K=1000, O=128 cat); rel half -> z4, root+b4 -> out
    {
        dim3 grid(1, MB);
        mmagemm<false, false, false, false, true><<<grid, T, SMEM>>>(
            z4, nullptr,
            h116, nullptr,
            w416, nullptr,
            nullptr, NNODES, D_H, 128, out, b4);
    }
    edge_agg_kernel<64><<<(NEDGES * 16 + T - 1) / T, T>>>(z4, 64, out, D_IN);
}

// round 15
// speedup vs baseline: 2.6649x; 1.1152x over previous
#include <cuda_runtime.h>
#include <cuda_fp16.h>
#include <cstdint>

#define NNODES 50000
#define NEDGES 200000
#define NGRAPH 2048
#define D_IN   64
#define D_H    1000
#define D_ENC  128

typedef __half f16;

// ---------------- scratch (static device allocations; no cudaMalloc) --------
__device__ float g_aggx [NNODES * D_IN];
__device__ float g_aggy [NNODES * D_ENC];
__device__ float g_h2f  [NNODES * D_ENC];
__device__ float g_aggh2[NNODES * D_ENC];
__device__ float g_z2   [NNODES * 256];   // cols 0..127 rel, 128..255 root
__device__ float g_z4   [NNODES * 64];    // z4 rel half only (root fused into out)
__device__ float g_sums [NGRAPH * D_ENC];
__device__ float g_counts[NGRAPH];
__device__ int   g_ei32[2 * NEDGES];
__device__ int   g_batch32[NNODES];
__device__ int   g_is64;

// fp16 operands (all single precision fp16)
__device__ __align__(16) f16 g_x16   [NNODES * D_IN];
__device__ __align__(16) f16 g_aggx16[NNODES * D_IN];
__device__ __align__(16) f16 g_h116  [(size_t)NNODES * D_H];
__device__ __align__(16) f16 g_h216  [NNODES * D_ENC];
__device__ __align__(16) f16 g_ah216 [NNODES * D_ENC];
__device__ __align__(16) f16 g_w1r16[D_H * D_IN];
__device__ __align__(16) f16 g_w1o16[D_H * D_IN];
__device__ __align__(16) f16 g_w216 [256 * D_H];
__device__ __align__(16) f16 g_w3r16[D_H * D_ENC];
__device__ __align__(16) f16 g_w3o16[D_H * D_ENC];
__device__ __align__(16) f16 g_w416 [128 * D_H];

// ---------------- helpers ----------------------------------------------------
__device__ __forceinline__ uint32_t pack2h(float v0, float v1) {
    uint32_t p;
    asm("cvt.rn.f16x2.f32 %0, %1, %2;" : "=r"(p) : "f"(v1), "f"(v0));
    return p;
}
__device__ __forceinline__ void red4(float* addr, float4 v) {
    asm volatile("red.global.add.v4.f32 [%0], {%1,%2,%3,%4};"
                 :: "l"(addr), "f"(v.x), "f"(v.y), "f"(v.z), "f"(v.w) : "memory");
}
__device__ __forceinline__ void red2(float* addr, float v0, float v1) {
    asm volatile("red.global.add.v2.f32 [%0], {%1,%2};"
                 :: "l"(addr), "f"(v0), "f"(v1) : "memory");
}
__device__ __forceinline__ void mma16816(float* d, const uint32_t* a, uint32_t b0, uint32_t b1) {
    asm volatile(
        "mma.sync.aligned.m16n8k16.row.col.f32.f16.f16.f32 "
        "{%0,%1,%2,%3}, {%4,%5,%6,%7}, {%8,%9}, {%0,%1,%2,%3};"
        : "+f"(d[0]), "+f"(d[1]), "+f"(d[2]), "+f"(d[3])
        : "r"(a[0]), "r"(a[1]), "r"(a[2]), "r"(a[3]), "r"(b0), "r"(b1));
}
__device__ __forceinline__ uint32_t cvta_s(const void* p) {
    uint32_t a;
    asm("{ .reg .u64 t; cvta.to.shared.u64 t, %1; cvt.u32.u64 %0, t; }" : "=r"(a) : "l"(p));
    return a;
}
#define LDMX4(r, a) \
    asm volatile("ldmatrix.sync.aligned.m8n8.x4.shared.b16 {%0,%1,%2,%3}, [%4];" \
        : "=r"((r)[0]), "=r"((r)[1]), "=r"((r)[2]), "=r"((r)[3]) : "r"(a))

// ---------------- dtype detection + conversion ------------------------------
__global__ void detect_kernel(const int* __restrict__ ei_raw) {
    int odd_zero = 1;
    #pragma unroll
    for (int i = 0; i < 16; ++i)
        if (ei_raw[2 * i + 1] != 0) odd_zero = 0;
    g_is64 = odd_zero;
}
__global__ void convert_kernel(const int* __restrict__ ei_raw, const int* __restrict__ batch_raw) {
    int i = blockIdx.x * blockDim.x + threadIdx.x;
    int is64 = g_is64;
    if (i < 2 * NEDGES) g_ei32[i] = is64 ? ei_raw[2 * i] : ei_raw[i];
    if (i < NNODES)     g_batch32[i] = is64 ? batch_raw[2 * i] : batch_raw[i];
}

// ---------------- merged utility kernels -------------------------------------
__global__ void zero_all_kernel() {
    float4 z = make_float4(0.f, 0.f, 0.f, 0.f);
    float4* aggy  = reinterpret_cast<float4*>(g_aggy);
    float4* aggh2 = reinterpret_cast<float4*>(g_aggh2);
    float4* aggx  = reinterpret_cast<float4*>(g_aggx);
    float4* sums  = reinterpret_cast<float4*>(g_sums);
    float4* cnts  = reinterpret_cast<float4*>(g_counts);
    for (int i = blockIdx.x * blockDim.x + threadIdx.x; i < NNODES * D_ENC / 4;
         i += gridDim.x * blockDim.x) {
        aggy[i] = z;
        aggh2[i] = z;
        if (i < NNODES * D_IN / 4) aggx[i] = z;
        if (i < NGRAPH * D_ENC / 4) sums[i] = z;
        if (i < NGRAPH / 4) cnts[i] = z;
    }
}
// weights + x -> fp16 single. one launch, 2 elements/iteration.
__global__ void split_static_kernel(
    const float* __restrict__ w1r, const float* __restrict__ w1o,
    const float* __restrict__ w2r, const float* __restrict__ w2o,
    const float* __restrict__ w3r, const float* __restrict__ w3o,
    const float* __restrict__ w4r, const float* __restrict__ w4o,
    const float* __restrict__ x) {
    const int P1 = D_H * D_IN / 2;     // 32000
    const int P2 = 128 * D_H / 2;      // 64000
    const int P3 = D_H * D_ENC / 2;    // 64000
    const int P4 = 64 * D_H / 2;       // 32000
    const int PX = NNODES * D_IN / 2;  // 1600000
    const int TOTP = 2 * P1 + 2 * P2 + 2 * P3 + 2 * P4 + PX;
    for (int p = blockIdx.x * blockDim.x + threadIdx.x; p < TOTP;
         p += gridDim.x * blockDim.x) {
        const float* src; f16* dst; int j = p;
        if (j < P1)              { src = w1r; dst = g_w1r16; }
        else if ((j -= P1) < P1) { src = w1o; dst = g_w1o16; }
        else if ((j -= P1) < P2) { src = w2r; dst = g_w216; }
        else if ((j -= P2) < P2) { src = w2o; dst = g_w216 + 2 * P2; }
        else if ((j -= P2) < P3) { src = w3r; dst = g_w3r16; }
        else if ((j -= P3) < P3) { src = w3o; dst = g_w3o16; }
        else if ((j -= P3) < P4) { src = w4r; dst = g_w416; }
        else if ((j -= P4) < P4) { src = w4o; dst = g_w416 + 2 * P4; }
        else { j -= P4;            src = x;   dst = g_x16; }
        int e = j * 2;
        float2 v = *reinterpret_cast<const float2*>(&src[e]);
        *reinterpret_cast<uint32_t*>(&dst[e]) = pack2h(v.x, v.y);
    }
}
// fp32 -> fp16 single convert
__global__ void cvt_kernel(const float* __restrict__ src, f16* __restrict__ dst, int n) {
    for (int e = (blockIdx.x * blockDim.x + threadIdx.x) * 2; e < n;
         e += gridDim.x * blockDim.x * 2) {
        float2 v = *reinterpret_cast<const float2*>(&src[e]);
        *reinterpret_cast<uint32_t*>(&dst[e]) = pack2h(v.x, v.y);
    }
}
// segment-sum over edges: 4 features per thread, vector RED (1 transaction)
template <int F>
__global__ void edge_agg_kernel(const float* __restrict__ feat, int featStride,
                                float* __restrict__ out, int outStride) {
    constexpr int V = F / 4;
    int idx = blockIdx.x * blockDim.x + threadIdx.x;
    int e = idx / V;
    int f = (idx % V) * 4;
    if (e >= NEDGES) return;
    int s = g_ei32[e];
    int d = g_ei32[NEDGES + e];
    float4 v = *reinterpret_cast<const float4*>(&feat[(size_t)s * featStride + f]);
    red4(&out[(size_t)d * outStride + f], v);
}
// fused: h2 = relu(aggy + z2_root + b2); fp32 + fp16 single; pool (2 el/thread)
__global__ void combine_pool_kernel(const float* __restrict__ b2) {
    int idx = blockIdx.x * blockDim.x + threadIdx.x;
    if (idx >= NNODES * 64) return;
    int i = idx >> 6, f = (idx & 63) * 2;
    float2 ag = *reinterpret_cast<const float2*>(&g_aggy[i * D_ENC + f]);
    float2 zr = *reinterpret_cast<const float2*>(&g_z2[(size_t)i * 256 + 128 + f]);
    float2 bb = *reinterpret_cast<const float2*>(&b2[f]);
    float v0 = fmaxf(ag.x + zr.x + bb.x, 0.f);
    float v1 = fmaxf(ag.y + zr.y + bb.y, 0.f);
    *reinterpret_cast<float2*>(&g_h2f[i * D_ENC + f]) = make_float2(v0, v1);
    *reinterpret_cast<uint32_t*>(&g_h216[i * D_ENC + f]) = pack2h(v0, v1);
    int b = g_batch32[i];
    red2(&g_sums[b * D_ENC + f], v0, v1);
    if (f == 0) atomicAdd(&g_counts[b], 1.f);
}
__global__ void encoded_kernel(float* __restrict__ enc) {
    int idx = blockIdx.x * blockDim.x + threadIdx.x;
    if (idx >= NGRAPH * D_ENC) return;
    int g = idx >> 7;
    enc[idx] = g_sums[idx] / fmaxf(g_counts[g], 1.f);
}

// ---------------- pipelined mma.sync fp16 single-pass GEMM -------------------
// C[M,O] = sum_sides A_s[M,K] @ W_s[O,K]^T; all operands single fp16.
// block 128x128; 8 warps (4m x 2n); warp tile 32x64.
// K-chunk 64, 2-stage cp.async pipeline, ldmatrix.x4 fragment loads, 2 CTA/SM.
#define CHUNK 64
#define SROW  144                 // 64 f16 (128B) + 16B pad; conflict-free walk
#define GTILE (128 * SROW)        // 18432
#define GSTAGE (2 * GTILE)        // 36864 (A, W)

template <bool DUAL_A, bool RELU, bool BIAS, bool F16OUT, bool OSPLIT>
__global__ void __launch_bounds__(256, 2) mmagemm(
    float* __restrict__ Cf, f16* __restrict__ C16,
    const f16* __restrict__ A1, const f16* __restrict__ A2,
    const f16* __restrict__ W1, const f16* __restrict__ W2,
    const float* __restrict__ bias, int M, int K, int O,
    float* __restrict__ C2, const float* __restrict__ bias2) {

    extern __shared__ char smraw[];
    const uint32_t smemBase = cvta_s(smraw);

    const int tid = threadIdx.x;
    const int wid = tid >> 5, lane = tid & 31;
    const int g = lane >> 2, t = lane & 3;
    const int warpM = (wid & 3) * 32, warpN = (wid >> 2) * 64;
    const int rowBase = blockIdx.y * 128, colBase = blockIdx.x * 128;

    const int laneRowA = (lane & 7) + ((lane & 8) ? 8 : 0);
    const int aK = (lane & 16) ? 16 : 0;
    const int laneRowW = (lane & 7) + ((lane & 16) ? 8 : 0);
    const int wK = (lane & 8) ? 16 : 0;
    uint32_t aoff[2], woff[4];
    #pragma unroll
    for (int mi = 0; mi < 2; ++mi)
        aoff[mi] = (uint32_t)((warpM + mi * 16 + laneRowA) * SROW + aK);
    #pragma unroll
    for (int p = 0; p < 4; ++p)
        woff[p] = (uint32_t)((warpN + p * 16 + laneRowW) * SROW + wK);

    float acc[2][8][4];
    #pragma unroll
    for (int a = 0; a < 2; ++a)
        #pragma unroll
        for (int b = 0; b < 8; ++b)
            #pragma unroll
            for (int c = 0; c < 4; ++c) acc[a][b][c] = 0.f;

    const int KC = (K + CHUNK - 1) / CHUNK;
    const int C = (DUAL_A ? 2 : 1) * KC;

    auto loadChunk = [&](int i, int stage) {
        int sIdx = DUAL_A ? (i / KC) : 0;
        int c = i - sIdx * KC;
        int k0 = c * CHUNK;
        const f16* A = (DUAL_A && sIdx) ? A2 : A1;
        const f16* W = (DUAL_A && sIdx) ? W2 : W1;
        uint32_t sb = smemBase + stage * GSTAGE;
        #pragma unroll
        for (int j = 0; j < 8; ++j) {
            int idx = tid + j * 256;          // 0..2047
            int tile = idx >> 10;             // 0=A, 1=W
            int r = (idx >> 3) & 127;
            int sg = idx & 7;
            int gk = k0 + sg * 8;
            const f16* src;
            int ok;
            if (tile == 0) {
                int gr = rowBase + r;
                ok = (gr < M) && (gk + 8 <= K);
                src = ok ? A + (size_t)gr * K + gk : A;
            } else {
                int gw = colBase + r;
                ok = (gw < O) && (gk + 8 <= K);
                src = ok ? W + (size_t)gw * K + gk : W;
            }
            uint32_t dst = sb + tile * GTILE + (uint32_t)(r * SROW + sg * 16);
            int sz = ok ? 16 : 0;
            asm volatile("cp.async.cg.shared.global [%0], [%1], 16, %2;"
                         :: "r"(dst), "l"(src), "r"(sz) : "memory");
        }
        asm volatile("cp.async.commit_group;" ::: "memory");
    };

    auto computeChunk = [&](int stage) {
        uint32_t sb = smemBase + stage * GSTAGE;
        uint32_t bA = sb, bW = sb + GTILE;
        #pragma unroll
        for (int ks = 0; ks < 4; ++ks) {
            uint32_t koff = ks * 32;
            uint32_t a[2][4];
            LDMX4(a[0], bA + aoff[0] + koff);
            LDMX4(a[1], bA + aoff[1] + koff);
            #pragma unroll
            for (int p = 0; p < 4; ++p) {
                uint32_t w[4];
                LDMX4(w, bW + woff[p] + koff);
                mma16816(acc[0][2 * p],     a[0], w[0], w[1]);
                mma16816(acc[1][2 * p],     a[1], w[0], w[1]);
                mma16816(acc[0][2 * p + 1], a[0], w[2], w[3]);
                mma16816(acc[1][2 * p + 1], a[1], w[2], w[3]);
            }
        }
    };

    loadChunk(0, 0);
    for (int c = 0; c < C; ++c) {
        if (c + 1 < C) {
            loadChunk(c + 1, (c + 1) & 1);
            asm volatile("cp.async.wait_group 1;" ::: "memory");
        } else {
            asm volatile("cp.async.wait_group 0;" ::: "memory");
        }
        __syncthreads();
        computeChunk(c & 1);
        __syncthreads();
    }

    // ---- epilogue (cols always even; pair stores unconditional) ----
    #pragma unroll
    for (int mi = 0; mi < 2; ++mi) {
        #pragma unroll
        for (int half = 0; half < 2; ++half) {
            int row = rowBase + warpM + mi * 16 + g + half * 8;
            if (row >= M) continue;
            #pragma unroll
            for (int ni = 0; ni < 8; ++ni) {
                int col = colBase + warpN + ni * 8 + 2 * t;
                if (col >= O) continue;
                float v0 = acc[mi][ni][half * 2 + 0];
                float v1 = acc[mi][ni][half * 2 + 1];
                if (BIAS) {
                    float2 bb = *reinterpret_cast<const float2*>(&bias[col]);
                    v0 += bb.x; v1 += bb.y;
                }
                if (RELU) { v0 = fmaxf(v0, 0.f); v1 = fmaxf(v1, 0.f); }
                if (OSPLIT) {
                    // O==128: cols<64 -> Cf[row*64+col] (rel); cols>=64 -> C2 + bias2 (root)
                    if (col < 64) {
                        *reinterpret_cast<float2*>(&Cf[(size_t)row * 64 + col]) =
                            make_float2(v0, v1);
                    } else {
                        int c2 = col - 64;
                        float2 bb = *reinterpret_cast<const float2*>(&bias2[c2]);
                        *reinterpret_cast<float2*>(&C2[(size_t)row * 64 + c2]) =
                            make_float2(v0 + bb.x, v1 + bb.y);
                    }
                } else if (F16OUT) {
                    *reinterpret_cast<uint32_t*>(&C16[(size_t)row * O + col]) = pack2h(v0, v1);
                } else {
                    *reinterpret_cast<float2*>(&Cf[(size_t)row * O + col]) =
                        make_float2(v0, v1);
                }
            }
        }
    }
}

// ---------------- launch ----------------------------------------------------
extern "C" void kernel_launch(void* const* d_in, const int* in_sizes, int n_in,
                              void* d_out, int out_size) {
    const float* x         = (const float*)d_in[0];
    const int*   ei_raw    = (const int*)d_in[1];
    const int*   batch_raw = (const int*)d_in[2];
    const float* W1_rel = (const float*)d_in[3];
    const float* b1     = (const float*)d_in[4];
    const float* W1_root= (const float*)d_in[5];
    const float* W2_rel = (const float*)d_in[6];
    const float* b2     = (const float*)d_in[7];
    const float* W2_root= (const float*)d_in[8];
    const float* W3_rel = (const float*)d_in[9];
    const float* b3     = (const float*)d_in[10];
    const float* W3_root= (const float*)d_in[11];
    const float* W4_rel = (const float*)d_in[12];
    const float* b4     = (const float*)d_in[13];
    const float* W4_root= (const float*)d_in[14];

    float* out = (float*)d_out;
    float* enc = out + (size_t)NNODES * D_IN;

    float *aggx, *aggy, *h2f, *aggh2, *z2, *z4;
    f16 *x16, *aggx16, *h116, *h216, *ah216;
    f16 *w1r16, *w1o16, *w216, *w3r16, *w3o16, *w416;
    cudaGetSymbolAddress((void**)&aggx, g_aggx);   cudaGetSymbolAddress((void**)&aggy, g_aggy);
    cudaGetSymbolAddress((void**)&h2f, g_h2f);     cudaGetSymbolAddress((void**)&aggh2, g_aggh2);
    cudaGetSymbolAddress((void**)&z2, g_z2);       cudaGetSymbolAddress((void**)&z4, g_z4);
    cudaGetSymbolAddress((void**)&x16, g_x16);     cudaGetSymbolAddress((void**)&aggx16, g_aggx16);
    cudaGetSymbolAddress((void**)&h116, g_h116);   cudaGetSymbolAddress((void**)&h216, g_h216);
    cudaGetSymbolAddress((void**)&ah216, g_ah216);
    cudaGetSymbolAddress((void**)&w1r16, g_w1r16); cudaGetSymbolAddress((void**)&w1o16, g_w1o16);
    cudaGetSymbolAddress((void**)&w216, g_w216);
    cudaGetSymbolAddress((void**)&w3r16, g_w3r16); cudaGetSymbolAddress((void**)&w3o16, g_w3o16);
    cudaGetSymbolAddress((void**)&w416, g_w416);

    const int T = 256;
    const int MB = (NNODES + 127) / 128;   // 391
    constexpr int SMEM = 2 * GSTAGE;       // 73728

    cudaFuncSetAttribute(mmagemm<true,  true,  true,  true,  false>, cudaFuncAttributeMaxDynamicSharedMemorySize, SMEM);
    cudaFuncSetAttribute(mmagemm<false, false, false, false, false>, cudaFuncAttributeMaxDynamicSharedMemorySize, SMEM);
    cudaFuncSetAttribute(mmagemm<false, false, false, false, true >, cudaFuncAttributeMaxDynamicSharedMemorySize, SMEM);

    // ---- setup
    detect_kernel<<<1, 1>>>(ei_raw);
    convert_kernel<<<(2 * NEDGES + T - 1) / T, T>>>(ei_raw, batch_raw);
    zero_all_kernel<<<1024, T>>>();
    split_static_kernel<<<1024, T>>>(W1_rel, W1_root, W2_rel, W2_root,
                                     W3_rel, W3_root, W4_rel, W4_root, x);

    // ---- L1: agg(x) then dual-A MMA -> h1 (fp16, relu, bias)
    edge_agg_kernel<64><<<(NEDGES * 16 + T - 1) / T, T>>>(x, D_IN, aggx, D_IN);
    cvt_kernel<<<512, T>>>(aggx, aggx16, NNODES * D_IN);
    {
        dim3 grid((D_H + 127) / 128, MB);
        mmagemm<true, true, true, true, false><<<grid, T, SMEM>>>(
            nullptr, h116,
            aggx16, x16,
            w1r16, w1o16,
            b1, NNODES, D_IN, D_H, nullptr, nullptr);
    }

    // ---- L2: single-A MMA (K=1000, O=256 cat) -> z2 fp32
    {
        dim3 grid(2, MB);
        mmagemm<false, false, false, false, false><<<grid, T, SMEM>>>(
            z2, nullptr,
            h116, nullptr,
            w216, nullptr,
            nullptr, NNODES, D_H, 256, nullptr, nullptr);
    }
    edge_agg_kernel<128><<<(NEDGES * 32 + T - 1) / T, T>>>(z2, 256, aggy, D_ENC);
    combine_pool_kernel<<<(NNODES * 64 + T - 1) / T, T>>>(b2);
    encoded_kernel<<<(NGRAPH * D_ENC + T - 1) / T, T>>>(enc);

    // ---- L3: agg(h2) then dual-A MMA -> h3 (reuse h1 buffer)
    edge_agg_kernel<128><<<(NEDGES * 32 + T - 1) / T, T>>>(h2f, D_ENC, aggh2, D_ENC);
    cvt_kernel<<<512, T>>>(aggh2, ah216, NNODES * D_ENC);
    {
        dim3 grid((D_H + 127) / 128, MB);
        mmagemm<true, true, true, true, false><<<grid, T, SMEM>>>(
            nullptr, h116,
            ah216, h216,
            w3r16, w3o16,
            b3, NNODES, D_ENC, D_H, nullptr, nullptr);
    }

    // ---- L4: single-A MMA (K=1000, O=128 cat); rel half -> z4, root+b4 -> out
    {
        dim3 grid(1, MB);
        mmagemm<false, false, false, false, true><<<grid, T, SMEM>>>(
            z4, nullptr,
            h116, nullptr,
            w416, nullptr,
            nullptr, NNODES, D_H, 128, out, b4);
    }
    edge_agg_kernel<64><<<(NEDGES * 16 + T - 1) / T, T>>>(z4, 64, out, D_IN);
}

// round 16
// speedup vs baseline: 2.9120x; 1.0928x over previous
#include <cuda_runtime.h>
#include <cuda_fp16.h>
#include <cstdint>

#define NNODES 50000
#define NEDGES 200000
#define NGRAPH 2048
#define D_IN   64
#define D_H    1000
#define D_ENC  128

typedef __half f16;

// ---------------- scratch (static device allocations; no cudaMalloc) --------
__device__ float g_aggy [NNODES * D_ENC];
__device__ float g_z2   [NNODES * 256];   // cols 0..127 rel, 128..255 root
__device__ float g_z4   [NNODES * 64];    // z4 rel half only (root fused into out)
__device__ float g_sums [NGRAPH * D_ENC];
__device__ float g_counts[NGRAPH];
__device__ int   g_ei32[2 * NEDGES];
__device__ int   g_batch32[NNODES];
__device__ int   g_is64;

// fp16 operands (all single precision fp16)
__device__ __align__(16) f16 g_x16   [NNODES * D_IN];
__device__ __align__(16) f16 g_aggx16[NNODES * D_IN];     // fp16 atomic agg target
__device__ __align__(16) f16 g_h116  [(size_t)NNODES * D_H];
__device__ __align__(16) f16 g_h216  [NNODES * D_ENC];
__device__ __align__(16) f16 g_ah216 [NNODES * D_ENC];    // fp16 atomic agg target
__device__ __align__(16) f16 g_w1r16[D_H * D_IN];
__device__ __align__(16) f16 g_w1o16[D_H * D_IN];
__device__ __align__(16) f16 g_w216 [256 * D_H];
__device__ __align__(16) f16 g_w3r16[D_H * D_ENC];
__device__ __align__(16) f16 g_w3o16[D_H * D_ENC];
__device__ __align__(16) f16 g_w416 [128 * D_H];

// ---------------- helpers ----------------------------------------------------
__device__ __forceinline__ uint32_t pack2h(float v0, float v1) {
    uint32_t p;
    asm("cvt.rn.f16x2.f32 %0, %1, %2;" : "=r"(p) : "f"(v1), "f"(v0));
    return p;
}
__device__ __forceinline__ void red4(float* addr, float4 v) {
    asm volatile("red.global.add.v4.f32 [%0], {%1,%2,%3,%4};"
                 :: "l"(addr), "f"(v.x), "f"(v.y), "f"(v.z), "f"(v.w) : "memory");
}
__device__ __forceinline__ void red2(float* addr, float v0, float v1) {
    asm volatile("red.global.add.v2.f32 [%0], {%1,%2};"
                 :: "l"(addr), "f"(v0), "f"(v1) : "memory");
}
__device__ __forceinline__ void red4h(f16* addr, uint4 v) {
    asm volatile("red.global.add.noftz.v4.f16x2 [%0], {%1,%2,%3,%4};"
                 :: "l"(addr), "r"(v.x), "r"(v.y), "r"(v.z), "r"(v.w) : "memory");
}
__device__ __forceinline__ void mma16816(float* d, const uint32_t* a, uint32_t b0, uint32_t b1) {
    asm volatile(
        "mma.sync.aligned.m16n8k16.row.col.f32.f16.f16.f32 "
        "{%0,%1,%2,%3}, {%4,%5,%6,%7}, {%8,%9}, {%0,%1,%2,%3};"
        : "+f"(d[0]), "+f"(d[1]), "+f"(d[2]), "+f"(d[3])
        : "r"(a[0]), "r"(a[1]), "r"(a[2]), "r"(a[3]), "r"(b0), "r"(b1));
}
__device__ __forceinline__ uint32_t cvta_s(const void* p) {
    uint32_t a;
    asm("{ .reg .u64 t; cvta.to.shared.u64 t, %1; cvt.u32.u64 %0, t; }" : "=r"(a) : "l"(p));
    return a;
}
#define LDMX4(r, a) \
    asm volatile("ldmatrix.sync.aligned.m8n8.x4.shared.b16 {%0,%1,%2,%3}, [%4];" \
        : "=r"((r)[0]), "=r"((r)[1]), "=r"((r)[2]), "=r"((r)[3]) : "r"(a))

// ---------------- dtype detection + conversion ------------------------------
__global__ void detect_kernel(const int* __restrict__ ei_raw) {
    int odd_zero = 1;
    #pragma unroll
    for (int i = 0; i < 16; ++i)
        if (ei_raw[2 * i + 1] != 0) odd_zero = 0;
    g_is64 = odd_zero;
}
__global__ void convert_kernel(const int* __restrict__ ei_raw, const int* __restrict__ batch_raw) {
    int i = blockIdx.x * blockDim.x + threadIdx.x;
    int is64 = g_is64;
    if (i < 2 * NEDGES) g_ei32[i] = is64 ? ei_raw[2 * i] : ei_raw[i];
    if (i < NNODES)     g_batch32[i] = is64 ? batch_raw[2 * i] : batch_raw[i];
}

// ---------------- merged utility kernels -------------------------------------
__global__ void zero_all_kernel() {
    float4 z = make_float4(0.f, 0.f, 0.f, 0.f);
    uint4  uz = make_uint4(0, 0, 0, 0);
    float4* aggy  = reinterpret_cast<float4*>(g_aggy);
    float4* sums  = reinterpret_cast<float4*>(g_sums);
    float4* cnts  = reinterpret_cast<float4*>(g_counts);
    uint4* aggx16 = reinterpret_cast<uint4*>(g_aggx16);     // 400000 uint4
    uint4* ah216  = reinterpret_cast<uint4*>(g_ah216);      // 800000 uint4
    for (int i = blockIdx.x * blockDim.x + threadIdx.x; i < NNODES * D_ENC / 4;
         i += gridDim.x * blockDim.x) {
        aggy[i] = z;
        if (i < NNODES * D_IN * 2 / 16) aggx16[i] = uz;
        if (i < NNODES * D_ENC * 2 / 16) ah216[i] = uz;
        if (i < NGRAPH * D_ENC / 4) sums[i] = z;
        if (i < NGRAPH / 4) cnts[i] = z;
    }
}
// weights + x -> fp16 single. one launch, 2 elements/iteration.
__global__ void split_static_kernel(
    const float* __restrict__ w1r, const float* __restrict__ w1o,
    const float* __restrict__ w2r, const float* __restrict__ w2o,
    const float* __restrict__ w3r, const float* __restrict__ w3o,
    const float* __restrict__ w4r, const float* __restrict__ w4o,
    const float* __restrict__ x) {
    const int P1 = D_H * D_IN / 2;     // 32000
    const int P2 = 128 * D_H / 2;      // 64000
    const int P3 = D_H * D_ENC / 2;    // 64000
    const int P4 = 64 * D_H / 2;       // 32000
    const int PX = NNODES * D_IN / 2;  // 1600000
    const int TOTP = 2 * P1 + 2 * P2 + 2 * P3 + 2 * P4 + PX;
    for (int p = blockIdx.x * blockDim.x + threadIdx.x; p < TOTP;
         p += gridDim.x * blockDim.x) {
        const float* src; f16* dst; int j = p;
        if (j < P1)              { src = w1r; dst = g_w1r16; }
        else if ((j -= P1) < P1) { src = w1o; dst = g_w1o16; }
        else if ((j -= P1) < P2) { src = w2r; dst = g_w216; }
        else if ((j -= P2) < P2) { src = w2o; dst = g_w216 + 2 * P2; }
        else if ((j -= P2) < P3) { src = w3r; dst = g_w3r16; }
        else if ((j -= P3) < P3) { src = w3o; dst = g_w3o16; }
        else if ((j -= P3) < P4) { src = w4r; dst = g_w416; }
        else if ((j -= P4) < P4) { src = w4o; dst = g_w416 + 2 * P4; }
        else { j -= P4;            src = x;   dst = g_x16; }
        int e = j * 2;
        float2 v = *reinterpret_cast<const float2*>(&src[e]);
        *reinterpret_cast<uint32_t*>(&dst[e]) = pack2h(v.x, v.y);
    }
}
// fp32 segment-sum over edges: 4 features per thread, vector RED
template <int F>
__global__ void edge_agg_kernel(const float* __restrict__ feat, int featStride,
                                float* __restrict__ out, int outStride) {
    constexpr int V = F / 4;
    int idx = blockIdx.x * blockDim.x + threadIdx.x;
    int e = idx / V;
    int f = (idx % V) * 4;
    if (e >= NEDGES) return;
    int s = g_ei32[e];
    int d = g_ei32[NEDGES + e];
    float4 v = *reinterpret_cast<const float4*>(&feat[(size_t)s * featStride + f]);
    red4(&out[(size_t)d * outStride + f], v);
}
// fp16 segment-sum over edges: 8 features per thread, one v4.f16x2 RED
template <int F>
__global__ void edge_agg_f16_kernel(const f16* __restrict__ feat,
                                    f16* __restrict__ out) {
    constexpr int V = F / 8;
    int idx = blockIdx.x * blockDim.x + threadIdx.x;
    int e = idx / V;
    int f = (idx % V) * 8;
    if (e >= NEDGES) return;
    int s = g_ei32[e];
    int d = g_ei32[NEDGES + e];
    uint4 v = *reinterpret_cast<const uint4*>(&feat[(size_t)s * F + f]);
    red4h(&out[(size_t)d * F + f], v);
}
// fused: h2 = relu(aggy + z2_root + b2); fp16 single; pool (2 el/thread)
__global__ void combine_pool_kernel(const float* __restrict__ b2) {
    int idx = blockIdx.x * blockDim.x + threadIdx.x;
    if (idx >= NNODES * 64) return;
    int i = idx >> 6, f = (idx & 63) * 2;
    float2 ag = *reinterpret_cast<const float2*>(&g_aggy[i * D_ENC + f]);
    float2 zr = *reinterpret_cast<const float2*>(&g_z2[(size_t)i * 256 + 128 + f]);
    float2 bb = *reinterpret_cast<const float2*>(&b2[f]);
    float v0 = fmaxf(ag.x + zr.x + bb.x, 0.f);
    float v1 = fmaxf(ag.y + zr.y + bb.y, 0.f);
    *reinterpret_cast<uint32_t*>(&g_h216[i * D_ENC + f]) = pack2h(v0, v1);
    int b = g_batch32[i];
    red2(&g_sums[b * D_ENC + f], v0, v1);
    if (f == 0) atomicAdd(&g_counts[b], 1.f);
}
__global__ void encoded_kernel(float* __restrict__ enc) {
    int idx = blockIdx.x * blockDim.x + threadIdx.x;
    if (idx >= NGRAPH * D_ENC) return;
    int g = idx >> 7;
    enc[idx] = g_sums[idx] / fmaxf(g_counts[g], 1.f);
}

// ---------------- pipelined mma.sync fp16 single-pass GEMM -------------------
// C[M,O] = sum_sides A_s[M,K] @ W_s[O,K]^T; all operands single fp16.
// block 128x128; 8 warps (4m x 2n); warp tile 32x64.
// K-chunk 64, 2-stage cp.async pipeline, ldmatrix.x4 fragment loads, 2 CTA/SM.
#define CHUNK 64
#define SROW  144                 // 64 f16 (128B) + 16B pad; conflict-free walk
#define GTILE (128 * SROW)        // 18432
#define GSTAGE (2 * GTILE)        // 36864 (A, W)

template <bool DUAL_A, bool RELU, bool BIAS, bool F16OUT, bool OSPLIT>
__global__ void __launch_bounds__(256, 2) mmagemm(
    float* __restrict__ Cf, f16* __restrict__ C16,
    const f16* __restrict__ A1, const f16* __restrict__ A2,
    const f16* __restrict__ W1, const f16* __restrict__ W2,
    const float* __restrict__ bias, int M, int K, int O,
    float* __restrict__ C2, const float* __restrict__ bias2) {

    extern __shared__ char smraw[];
    const uint32_t smemBase = cvta_s(smraw);

    const int tid = threadIdx.x;
    const int wid = tid >> 5, lane = tid & 31;
    const int g = lane >> 2, t = lane & 3;
    const int warpM = (wid & 3) * 32, warpN = (wid >> 2) * 64;
    const int rowBase = blockIdx.y * 128, colBase = blockIdx.x * 128;

    const int laneRowA = (lane & 7) + ((lane & 8) ? 8 : 0);
    const int aK = (lane & 16) ? 16 : 0;
    const int laneRowW = (lane & 7) + ((lane & 16) ? 8 : 0);
    const int wK = (lane & 8) ? 16 : 0;
    uint32_t aoff[2], woff[4];
    #pragma unroll
    for (int mi = 0; mi < 2; ++mi)
        aoff[mi] = (uint32_t)((warpM + mi * 16 + laneRowA) * SROW + aK);
    #pragma unroll
    for (int p = 0; p < 4; ++p)
        woff[p] = (uint32_t)((warpN + p * 16 + laneRowW) * SROW + wK);

    float acc[2][8][4];
    #pragma unroll
    for (int a = 0; a < 2; ++a)
        #pragma unroll
        for (int b = 0; b < 8; ++b)
            #pragma unroll
            for (int c = 0; c < 4; ++c) acc[a][b][c] = 0.f;

    const int KC = (K + CHUNK - 1) / CHUNK;
    const int C = (DUAL_A ? 2 : 1) * KC;

    auto loadChunk = [&](int i, int stage) {
        int sIdx = DUAL_A ? (i / KC) : 0;
        int c = i - sIdx * KC;
        int k0 = c * CHUNK;
        const f16* A = (DUAL_A && sIdx) ? A2 : A1;
        const f16* W = (DUAL_A && sIdx) ? W2 : W1;
        uint32_t sb = smemBase + stage * GSTAGE;
        #pragma unroll
        for (int j = 0; j < 8; ++j) {
            int idx = tid + j * 256;          // 0..2047
            int tile = idx >> 10;             // 0=A, 1=W
            int r = (idx >> 3) & 127;
            int sg = idx & 7;
            int gk = k0 + sg * 8;
            const f16* src;
            int ok;
            if (tile == 0) {
                int gr = rowBase + r;
                ok = (gr < M) && (gk + 8 <= K);
                src = ok ? A + (size_t)gr * K + gk : A;
            } else {
                int gw = colBase + r;
                ok = (gw < O) && (gk + 8 <= K);
                src = ok ? W + (size_t)gw * K + gk : W;
            }
            uint32_t dst = sb + tile * GTILE + (uint32_t)(r * SROW + sg * 16);
            int sz = ok ? 16 : 0;
            asm volatile("cp.async.cg.shared.global [%0], [%1], 16, %2;"
                         :: "r"(dst), "l"(src), "r"(sz) : "memory");
        }
        asm volatile("cp.async.commit_group;" ::: "memory");
    };

    auto computeChunk = [&](int stage) {
        uint32_t sb = smemBase + stage * GSTAGE;
        uint32_t bA = sb, bW = sb + GTILE;
        #pragma unroll
        for (int ks = 0; ks < 4; ++ks) {
            uint32_t koff = ks * 32;
            uint32_t a[2][4];
            LDMX4(a[0], bA + aoff[0] + koff);
            LDMX4(a[1], bA + aoff[1] + koff);
            #pragma unroll
            for (int p = 0; p < 4; ++p) {
                uint32_t w[4];
                LDMX4(w, bW + woff[p] + koff);
                mma16816(acc[0][2 * p],     a[0], w[0], w[1]);
                mma16816(acc[1][2 * p],     a[1], w[0], w[1]);
                mma16816(acc[0][2 * p + 1], a[0], w[2], w[3]);
                mma16816(acc[1][2 * p + 1], a[1], w[2], w[3]);
            }
        }
    };

    loadChunk(0, 0);
    for (int c = 0; c < C; ++c) {
        if (c + 1 < C) {
            loadChunk(c + 1, (c + 1) & 1);
            asm volatile("cp.async.wait_group 1;" ::: "memory");
        } else {
            asm volatile("cp.async.wait_group 0;" ::: "memory");
        }
        __syncthreads();
        computeChunk(c & 1);
        __syncthreads();
    }

    // ---- epilogue (cols always even; pair stores unconditional) ----
    #pragma unroll
    for (int mi = 0; mi < 2; ++mi) {
        #pragma unroll
        for (int half = 0; half < 2; ++half) {
            int row = rowBase + warpM + mi * 16 + g + half * 8;
            if (row >= M) continue;
            #pragma unroll
            for (int ni = 0; ni < 8; ++ni) {
                int col = colBase + warpN + ni * 8 + 2 * t;
                if (col >= O) continue;
                float v0 = acc[mi][ni][half * 2 + 0];
                float v1 = acc[mi][ni][half * 2 + 1];
                if (BIAS) {
                    float2 bb = *reinterpret_cast<const float2*>(&bias[col]);
                    v0 += bb.x; v1 += bb.y;
                }
                if (RELU) { v0 = fmaxf(v0, 0.f); v1 = fmaxf(v1, 0.f); }
                if (OSPLIT) {
                    // O==128: cols<64 -> Cf[row*64+col] (rel); cols>=64 -> C2 + bias2 (root)
                    if (col < 64) {
                        *reinterpret_cast<float2*>(&Cf[(size_t)row * 64 + col]) =
                            make_float2(v0, v1);
                    } else {
                        int c2 = col - 64;
                        float2 bb = *reinterpret_cast<const float2*>(&bias2[c2]);
                        *reinterpret_cast<float2*>(&C2[(size_t)row * 64 + c2]) =
                            make_float2(v0 + bb.x, v1 + bb.y);
                    }
                } else if (F16OUT) {
                    *reinterpret_cast<uint32_t*>(&C16[(size_t)row * O + col]) = pack2h(v0, v1);
                } else {
                    *reinterpret_cast<float2*>(&Cf[(size_t)row * O + col]) =
                        make_float2(v0, v1);
                }
            }
        }
    }
}

// ---------------- launch ----------------------------------------------------
extern "C" void kernel_launch(void* const* d_in, const int* in_sizes, int n_in,
                              void* d_out, int out_size) {
    const float* x         = (const float*)d_in[0];
    const int*   ei_raw    = (const int*)d_in[1];
    const int*   batch_raw = (const int*)d_in[2];
    const float* W1_rel = (const float*)d_in[3];
    const float* b1     = (const float*)d_in[4];
    const float* W1_root= (const float*)d_in[5];
    const float* W2_rel = (const float*)d_in[6];
    const float* b2     = (const float*)d_in[7];
    const float* W2_root= (const float*)d_in[8];
    const float* W3_rel = (const float*)d_in[9];
    const float* b3     = (const float*)d_in[10];
    const float* W3_root= (const float*)d_in[11];
    const float* W4_rel = (const float*)d_in[12];
    const float* b4     = (const float*)d_in[13];
    const float* W4_root= (const float*)d_in[14];

    float* out = (float*)d_out;
    float* enc = out + (size_t)NNODES * D_IN;

    float *aggy, *z2, *z4;
    f16 *x16, *aggx16, *h116, *h216, *ah216;
    f16 *w1r16, *w1o16, *w216, *w3r16, *w3o16, *w416;
    cudaGetSymbolAddress((void**)&aggy, g_aggy);
    cudaGetSymbolAddress((void**)&z2, g_z2);       cudaGetSymbolAddress((void**)&z4, g_z4);
    cudaGetSymbolAddress((void**)&x16, g_x16);     cudaGetSymbolAddress((void**)&aggx16, g_aggx16);
    cudaGetSymbolAddress((void**)&h116, g_h116);   cudaGetSymbolAddress((void**)&h216, g_h216);
    cudaGetSymbolAddress((void**)&ah216, g_ah216);
    cudaGetSymbolAddress((void**)&w1r16, g_w1r16); cudaGetSymbolAddress((void**)&w1o16, g_w1o16);
    cudaGetSymbolAddress((void**)&w216, g_w216);
    cudaGetSymbolAddress((void**)&w3r16, g_w3r16); cudaGetSymbolAddress((void**)&w3o16, g_w3o16);
    cudaGetSymbolAddress((void**)&w416, g_w416);

    const int T = 256;
    const int MB = (NNODES + 127) / 128;   // 391
    constexpr int SMEM = 2 * GSTAGE;       // 73728

    cudaFuncSetAttribute(mmagemm<true,  true,  true,  true,  false>, cudaFuncAttributeMaxDynamicSharedMemorySize, SMEM);
    cudaFuncSetAttribute(mmagemm<false, false, false, false, false>, cudaFuncAttributeMaxDynamicSharedMemorySize, SMEM);
    cudaFuncSetAttribute(mmagemm<false, false, false, false, true >, cudaFuncAttributeMaxDynamicSharedMemorySize, SMEM);

    // ---- setup
    detect_kernel<<<1, 1>>>(ei_raw);
    convert_kernel<<<(2 * NEDGES + T - 1) / T, T>>>(ei_raw, batch_raw);
    zero_all_kernel<<<1024, T>>>();
    split_static_kernel<<<1024, T>>>(W1_rel, W1_root, W2_rel, W2_root,
                                     W3_rel, W3_root, W4_rel, W4_root, x);

    // ---- L1: fp16 agg(x16) then dual-A MMA -> h1 (fp16, relu, bias)
    edge_agg_f16_kernel<64><<<(NEDGES * 8 + T - 1) / T, T>>>(x16, aggx16);
    {
        dim3 grid((D_H + 127) / 128, MB);
        mmagemm<true, true, true, true, false><<<grid, T, SMEM>>>(
            nullptr, h116,
            aggx16, x16,
            w1r16, w1o16,
            b1, NNODES, D_IN, D_H, nullptr, nullptr);
    }

    // ---- L2: single-A MMA (K=1000, O=256 cat) -> z2 fp32
    {
        dim3 grid(2, MB);
        mmagemm<false, false, false, false, false><<<grid, T, SMEM>>>(
            z2, nullptr,
            h116, nullptr,
            w216, nullptr,
            nullptr, NNODES, D_H, 256, nullptr, nullptr);
    }
    edge_agg_kernel<128><<<(NEDGES * 32 + T - 1) / T, T>>>(z2, 256, aggy, D_ENC);
    combine_pool_kernel<<<(NNODES * 64 + T - 1) / T, T>>>(b2);
    encoded_kernel<<<(NGRAPH * D_ENC + T - 1) / T, T>>>(enc);

    // ---- L3: fp16 agg(h216) then dual-A MMA -> h3 (reuse h1 buffer)
    edge_agg_f16_kernel<128><<<(NEDGES * 16 + T - 1) / T, T>>>(h216, ah216);
    {
        dim3 grid((D_H + 127) / 128, MB);
        mmagemm<true, true, true, true, false><<<grid, T, SMEM>>>(
            nullptr, h116,
            ah216, h216,
            w3r16, w3o16,
            b3, NNODES, D_ENC, D_H, nullptr, nullptr);
    }

    // ---- L4: single-A MMA (K=1000, O=128 cat); rel half -> z4, root+b4 -> out
    {
        dim3 grid(1, MB);
        mmagemm<false, false, false, false, true><<<grid, T, SMEM>>>(
            z4, nullptr,
            h116, nullptr,
            w416, nullptr,
            nullptr, NNODES, D_H, 128, out, b4);
    }
    edge_agg_kernel<64><<<(NEDGES * 16 + T - 1) / T, T>>>(z4, 64, out, D_IN);
}

// round 17
// speedup vs baseline: 3.0355x; 1.0424x over previous
#include <cuda_runtime.h>
#include <cuda_fp16.h>
#include <cstdint>

#define NNODES 50000
#define NEDGES 200000
#define NGRAPH 2048
#define D_IN   64
#define D_H    1000
#define D_ENC  128

typedef __half f16;

// ---------------- scratch (static device allocations; no cudaMalloc) --------
__device__ float g_z2root[NNODES * 128];  // z2 root half (fp32, feeds pool path)
__device__ float g_z4   [NNODES * 64];    // z4 rel half only (root fused into out)
__device__ float g_sums [NGRAPH * D_ENC];
__device__ float g_counts[NGRAPH];
__device__ int   g_ei32[2 * NEDGES];
__device__ int   g_batch32[NNODES];
__device__ int   g_is64;

// fp16 operands
__device__ __align__(16) f16 g_x16   [NNODES * D_IN];
__device__ __align__(16) f16 g_aggx16[NNODES * D_IN];     // fp16 atomic agg target
__device__ __align__(16) f16 g_h116  [(size_t)NNODES * D_H];
__device__ __align__(16) f16 g_h216  [NNODES * D_ENC];
__device__ __align__(16) f16 g_ah216 [NNODES * D_ENC];    // fp16 atomic agg target
__device__ __align__(16) f16 g_z2r16 [NNODES * 128];      // z2 rel half fp16
__device__ __align__(16) f16 g_aggy16[NNODES * 128];      // fp16 atomic agg target
__device__ __align__(16) f16 g_w1r16[D_H * D_IN];
__device__ __align__(16) f16 g_w1o16[D_H * D_IN];
__device__ __align__(16) f16 g_w216 [256 * D_H];
__device__ __align__(16) f16 g_w3r16[D_H * D_ENC];
__device__ __align__(16) f16 g_w3o16[D_H * D_ENC];
__device__ __align__(16) f16 g_w416 [128 * D_H];

// ---------------- helpers ----------------------------------------------------
__device__ __forceinline__ uint32_t pack2h(float v0, float v1) {
    uint32_t p;
    asm("cvt.rn.f16x2.f32 %0, %1, %2;" : "=r"(p) : "f"(v1), "f"(v0));
    return p;
}
__device__ __forceinline__ void red4(float* addr, float4 v) {
    asm volatile("red.global.add.v4.f32 [%0], {%1,%2,%3,%4};"
                 :: "l"(addr), "f"(v.x), "f"(v.y), "f"(v.z), "f"(v.w) : "memory");
}
__device__ __forceinline__ void red2(float* addr, float v0, float v1) {
    asm volatile("red.global.add.v2.f32 [%0], {%1,%2};"
                 :: "l"(addr), "f"(v0), "f"(v1) : "memory");
}
__device__ __forceinline__ void red4h(f16* addr, uint4 v) {
    asm volatile("red.global.add.noftz.v4.f16x2 [%0], {%1,%2,%3,%4};"
                 :: "l"(addr), "r"(v.x), "r"(v.y), "r"(v.z), "r"(v.w) : "memory");
}
__device__ __forceinline__ void mma16816(float* d, const uint32_t* a, uint32_t b0, uint32_t b1) {
    asm volatile(
        "mma.sync.aligned.m16n8k16.row.col.f32.f16.f16.f32 "
        "{%0,%1,%2,%3}, {%4,%5,%6,%7}, {%8,%9}, {%0,%1,%2,%3};"
        : "+f"(d[0]), "+f"(d[1]), "+f"(d[2]), "+f"(d[3])
        : "r"(a[0]), "r"(a[1]), "r"(a[2]), "r"(a[3]), "r"(b0), "r"(b1));
}
__device__ __forceinline__ uint32_t cvta_s(const void* p) {
    uint32_t a;
    asm("{ .reg .u64 t; cvta.to.shared.u64 t, %1; cvt.u32.u64 %0, t; }" : "=r"(a) : "l"(p));
    return a;
}
#define LDMX4(r, a) \
    asm volatile("ldmatrix.sync.aligned.m8n8.x4.shared.b16 {%0,%1,%2,%3}, [%4];" \
        : "=r"((r)[0]), "=r"((r)[1]), "=r"((r)[2]), "=r"((r)[3]) : "r"(a))

// ---------------- dtype detection + conversion ------------------------------
__global__ void detect_kernel(const int* __restrict__ ei_raw) {
    int odd_zero = 1;
    #pragma unroll
    for (int i = 0; i < 16; ++i)
        if (ei_raw[2 * i + 1] != 0) odd_zero = 0;
    g_is64 = odd_zero;
}
__global__ void convert_kernel(const int* __restrict__ ei_raw, const int* __restrict__ batch_raw) {
    int i = blockIdx.x * blockDim.x + threadIdx.x;
    int is64 = g_is64;
    if (i < 2 * NEDGES) g_ei32[i] = is64 ? ei_raw[2 * i] : ei_raw[i];
    if (i < NNODES)     g_batch32[i] = is64 ? batch_raw[2 * i] : batch_raw[i];
}

// ---------------- merged utility kernels -------------------------------------
__global__ void zero_all_kernel() {
    float4 z = make_float4(0.f, 0.f, 0.f, 0.f);
    uint4  uz = make_uint4(0, 0, 0, 0);
    float4* sums  = reinterpret_cast<float4*>(g_sums);
    float4* cnts  = reinterpret_cast<float4*>(g_counts);
    uint4* aggx16 = reinterpret_cast<uint4*>(g_aggx16);     // 400000 uint4
    uint4* ah216  = reinterpret_cast<uint4*>(g_ah216);      // 800000 uint4
    uint4* aggy16 = reinterpret_cast<uint4*>(g_aggy16);     // 800000 uint4
    for (int i = blockIdx.x * blockDim.x + threadIdx.x; i < 800000;
         i += gridDim.x * blockDim.x) {
        ah216[i] = uz;
        aggy16[i] = uz;
        if (i < 400000) aggx16[i] = uz;
        if (i < NGRAPH * D_ENC / 4) sums[i] = z;
        if (i < NGRAPH / 4) cnts[i] = z;
    }
}
// weights + x -> fp16 single. one launch, 2 elements/iteration.
__global__ void split_static_kernel(
    const float* __restrict__ w1r, const float* __restrict__ w1o,
    const float* __restrict__ w2r, const float* __restrict__ w2o,
    const float* __restrict__ w3r, const float* __restrict__ w3o,
    const float* __restrict__ w4r, const float* __restrict__ w4o,
    const float* __restrict__ x) {
    const int P1 = D_H * D_IN / 2;     // 32000
    const int P2 = 128 * D_H / 2;      // 64000
    const int P3 = D_H * D_ENC / 2;    // 64000
    const int P4 = 64 * D_H / 2;       // 32000
    const int PX = NNODES * D_IN / 2;  // 1600000
    const int TOTP = 2 * P1 + 2 * P2 + 2 * P3 + 2 * P4 + PX;
    for (int p = blockIdx.x * blockDim.x + threadIdx.x; p < TOTP;
         p += gridDim.x * blockDim.x) {
        const float* src; f16* dst; int j = p;
        if (j < P1)              { src = w1r; dst = g_w1r16; }
        else if ((j -= P1) < P1) { src = w1o; dst = g_w1o16; }
        else if ((j -= P1) < P2) { src = w2r; dst = g_w216; }
        else if ((j -= P2) < P2) { src = w2o; dst = g_w216 + 2 * P2; }
        else if ((j -= P2) < P3) { src = w3r; dst = g_w3r16; }
        else if ((j -= P3) < P3) { src = w3o; dst = g_w3o16; }
        else if ((j -= P3) < P4) { src = w4r; dst = g_w416; }
        else if ((j -= P4) < P4) { src = w4o; dst = g_w416 + 2 * P4; }
        else { j -= P4;            src = x;   dst = g_x16; }
        int e = j * 2;
        float2 v = *reinterpret_cast<const float2*>(&src[e]);
        *reinterpret_cast<uint32_t*>(&dst[e]) = pack2h(v.x, v.y);
    }
}
// fp32 segment-sum over edges: 4 features per thread, vector RED
template <int F>
__global__ void edge_agg_kernel(const float* __restrict__ feat, int featStride,
                                float* __restrict__ out, int outStride) {
    constexpr int V = F / 4;
    int idx = blockIdx.x * blockDim.x + threadIdx.x;
    int e = idx / V;
    int f = (idx % V) * 4;
    if (e >= NEDGES) return;
    int s = g_ei32[e];
    int d = g_ei32[NEDGES + e];
    float4 v = *reinterpret_cast<const float4*>(&feat[(size_t)s * featStride + f]);
    red4(&out[(size_t)d * outStride + f], v);
}
// fp16 segment-sum over edges: 8 features per thread, one v4.f16x2 RED
template <int F>
__global__ void edge_agg_f16_kernel(const f16* __restrict__ feat,
                                    f16* __restrict__ out) {
    constexpr int V = F / 8;
    int idx = blockIdx.x * blockDim.x + threadIdx.x;
    int e = idx / V;
    int f = (idx % V) * 8;
    if (e >= NEDGES) return;
    int s = g_ei32[e];
    int d = g_ei32[NEDGES + e];
    uint4 v = *reinterpret_cast<const uint4*>(&feat[(size_t)s * F + f]);
    red4h(&out[(size_t)d * F + f], v);
}
// fused: h2 = relu(aggy16 + z2root + b2); fp16 single; pool (2 el/thread)
__global__ void combine_pool_kernel(const float* __restrict__ b2) {
    int idx = blockIdx.x * blockDim.x + threadIdx.x;
    if (idx >= NNODES * 64) return;
    int i = idx >> 6, f = (idx & 63) * 2;
    uint32_t agp = *reinterpret_cast<const uint32_t*>(&g_aggy16[i * D_ENC + f]);
    __half2 agh = *reinterpret_cast<__half2*>(&agp);
    float2 zr = *reinterpret_cast<const float2*>(&g_z2root[(size_t)i * 128 + f]);
    float2 bb = *reinterpret_cast<const float2*>(&b2[f]);
    float v0 = fmaxf(__low2float(agh) + zr.x + bb.x, 0.f);
    float v1 = fmaxf(__high2float(agh) + zr.y + bb.y, 0.f);
    *reinterpret_cast<uint32_t*>(&g_h216[i * D_ENC + f]) = pack2h(v0, v1);
    int b = g_batch32[i];
    red2(&g_sums[b * D_ENC + f], v0, v1);
    if (f == 0) atomicAdd(&g_counts[b], 1.f);
}
__global__ void encoded_kernel(float* __restrict__ enc) {
    int idx = blockIdx.x * blockDim.x + threadIdx.x;
    if (idx >= NGRAPH * D_ENC) return;
    int g = idx >> 7;
    enc[idx] = g_sums[idx] / fmaxf(g_counts[g], 1.f);
}

// ---------------- pipelined mma.sync fp16 single-pass GEMM -------------------
// C[M,O] = sum_sides A_s[M,K] @ W_s[O,K]^T; all operands single fp16.
// block 128x128; 8 warps (4m x 2n); warp tile 32x64.
// K-chunk 64, 2-stage cp.async pipeline, ldmatrix.x4 fragment loads, 2 CTA/SM.
#define CHUNK 64
#define SROW  144                 // 64 f16 (128B) + 16B pad; conflict-free walk
#define GTILE (128 * SROW)        // 18432
#define GSTAGE (2 * GTILE)        // 36864 (A, W)

// MODE: OSPLIT (L4): col<64 -> Cf fp32 (ldC=64); col>=64 -> C2 + bias2 fp32
//       ZSPLIT (L2): col<128 -> C16 fp16 (ld=128); col>=128 -> C2 fp32 (ld=128)
template <bool DUAL_A, bool RELU, bool BIAS, bool F16OUT, bool OSPLIT, bool ZSPLIT>
__global__ void __launch_bounds__(256, 2) mmagemm(
    float* __restrict__ Cf, f16* __restrict__ C16,
    const f16* __restrict__ A1, const f16* __restrict__ A2,
    const f16* __restrict__ W1, const f16* __restrict__ W2,
    const float* __restrict__ bias, int M, int K, int O,
    float* __restrict__ C2, const float* __restrict__ bias2) {

    extern __shared__ char smraw[];
    const uint32_t smemBase = cvta_s(smraw);

    const int tid = threadIdx.x;
    const int wid = tid >> 5, lane = tid & 31;
    const int g = lane >> 2, t = lane & 3;
    const int warpM = (wid & 3) * 32, warpN = (wid >> 2) * 64;
    const int rowBase = blockIdx.y * 128, colBase = blockIdx.x * 128;

    const int laneRowA = (lane & 7) + ((lane & 8) ? 8 : 0);
    const int aK = (lane & 16) ? 16 : 0;
    const int laneRowW = (lane & 7) + ((lane & 16) ? 8 : 0);
    const int wK = (lane & 8) ? 16 : 0;
    uint32_t aoff[2], woff[4];
    #pragma unroll
    for (int mi = 0; mi < 2; ++mi)
        aoff[mi] = (uint32_t)((warpM + mi * 16 + laneRowA) * SROW + aK);
    #pragma unroll
    for (int p = 0; p < 4; ++p)
        woff[p] = (uint32_t)((warpN + p * 16 + laneRowW) * SROW + wK);

    float acc[2][8][4];
    #pragma unroll
    for (int a = 0; a < 2; ++a)
        #pragma unroll
        for (int b = 0; b < 8; ++b)
            #pragma unroll
            for (int c = 0; c < 4; ++c) acc[a][b][c] = 0.f;

    const int KC = (K + CHUNK - 1) / CHUNK;
    const int C = (DUAL_A ? 2 : 1) * KC;

    auto loadChunk = [&](int i, int stage) {
        int sIdx = DUAL_A ? (i / KC) : 0;
        int c = i - sIdx * KC;
        int k0 = c * CHUNK;
        const f16* A = (DUAL_A && sIdx) ? A2 : A1;
        const f16* W = (DUAL_A && sIdx) ? W2 : W1;
        uint32_t sb = smemBase + stage * GSTAGE;
        #pragma unroll
        for (int j = 0; j < 8; ++j) {
            int idx = tid + j * 256;          // 0..2047
            int tile = idx >> 10;             // 0=A, 1=W
            int r = (idx >> 3) & 127;
            int sg = idx & 7;
            int gk = k0 + sg * 8;
            const f16* src;
            int ok;
            if (tile == 0) {
                int gr = rowBase + r;
                ok = (gr < M) && (gk + 8 <= K);
                src = ok ? A + (size_t)gr * K + gk : A;
            } else {
                int gw = colBase + r;
                ok = (gw < O) && (gk + 8 <= K);
                src = ok ? W + (size_t)gw * K + gk : W;
            }
            uint32_t dst = sb + tile * GTILE + (uint32_t)(r * SROW + sg * 16);
            int sz = ok ? 16 : 0;
            asm volatile("cp.async.cg.shared.global [%0], [%1], 16, %2;"
                         :: "r"(dst), "l"(src), "r"(sz) : "memory");
        }
        asm volatile("cp.async.commit_group;" ::: "memory");
    };

    auto computeChunk = [&](int stage) {
        uint32_t sb = smemBase + stage * GSTAGE;
        uint32_t bA = sb, bW = sb + GTILE;
        #pragma unroll
        for (int ks = 0; ks < 4; ++ks) {
            uint32_t koff = ks * 32;
            uint32_t a[2][4];
            LDMX4(a[0], bA + aoff[0] + koff);
            LDMX4(a[1], bA + aoff[1] + koff);
            #pragma unroll
            for (int p = 0; p < 4; ++p) {
                uint32_t w[4];
                LDMX4(w, bW + woff[p] + koff);
                mma16816(acc[0][2 * p],     a[0], w[0], w[1]);
                mma16816(acc[1][2 * p],     a[1], w[0], w[1]);
                mma16816(acc[0][2 * p + 1], a[0], w[2], w[3]);
                mma16816(acc[1][2 * p + 1], a[1], w[2], w[3]);
            }
        }
    };

    loadChunk(0, 0);
    for (int c = 0; c < C; ++c) {
        if (c + 1 < C) {
            loadChunk(c + 1, (c + 1) & 1);
            asm volatile("cp.async.wait_group 1;" ::: "memory");
        } else {
            asm volatile("cp.async.wait_group 0;" ::: "memory");
        }
        __syncthreads();
        computeChunk(c & 1);
        __syncthreads();
    }

    // ---- epilogue (cols always even; pair stores unconditional) ----
    #pragma unroll
    for (int mi = 0; mi < 2; ++mi) {
        #pragma unroll
        for (int half = 0; half < 2; ++half) {
            int row = rowBase + warpM + mi * 16 + g + half * 8;
            if (row >= M) continue;
            #pragma unroll
            for (int ni = 0; ni < 8; ++ni) {
                int col = colBase + warpN + ni * 8 + 2 * t;
                if (col >= O) continue;
                float v0 = acc[mi][ni][half * 2 + 0];
                float v1 = acc[mi][ni][half * 2 + 1];
                if (BIAS) {
                    float2 bb = *reinterpret_cast<const float2*>(&bias[col]);
                    v0 += bb.x; v1 += bb.y;
                }
                if (RELU) { v0 = fmaxf(v0, 0.f); v1 = fmaxf(v1, 0.f); }
                if (OSPLIT) {
                    // O==128: cols<64 -> Cf[row*64+col] (rel); cols>=64 -> C2 + bias2 (root)
                    if (col < 64) {
                        *reinterpret_cast<float2*>(&Cf[(size_t)row * 64 + col]) =
                            make_float2(v0, v1);
                    } else {
                        int c2 = col - 64;
                        float2 bb = *reinterpret_cast<const float2*>(&bias2[c2]);
                        *reinterpret_cast<float2*>(&C2[(size_t)row * 64 + c2]) =
                            make_float2(v0 + bb.x, v1 + bb.y);
                    }
                } else if (ZSPLIT) {
                    // O==256: cols<128 -> C16 fp16 (rel); cols>=128 -> C2 fp32 (root)
                    if (col < 128) {
                        *reinterpret_cast<uint32_t*>(&C16[(size_t)row * 128 + col]) =
                            pack2h(v0, v1);
                    } else {
                        int c2 = col - 128;
                        *reinterpret_cast<float2*>(&C2[(size_t)row * 128 + c2]) =
                            make_float2(v0, v1);
                    }
                } else if (F16OUT) {
                    *reinterpret_cast<uint32_t*>(&C16[(size_t)row * O + col]) = pack2h(v0, v1);
                } else {
                    *reinterpret_cast<float2*>(&Cf[(size_t)row * O + col]) =
                        make_float2(v0, v1);
                }
            }
        }
    }
}

// ---------------- launch ----------------------------------------------------
extern "C" void kernel_launch(void* const* d_in, const int* in_sizes, int n_in,
                              void* d_out, int out_size) {
    const float* x         = (const float*)d_in[0];
    const int*   ei_raw    = (const int*)d_in[1];
    const int*   batch_raw = (const int*)d_in[2];
    const float* W1_rel = (const float*)d_in[3];
    const float* b1     = (const float*)d_in[4];
    const float* W1_root= (const float*)d_in[5];
    const float* W2_rel = (const float*)d_in[6];
    const float* b2     = (const float*)d_in[7];
    const float* W2_root= (const float*)d_in[8];
    const float* W3_rel = (const float*)d_in[9];
    const float* b3     = (const float*)d_in[10];
    const float* W3_root= (const float*)d_in[11];
    const float* W4_rel = (const float*)d_in[12];
    const float* b4     = (const float*)d_in[13];
    const float* W4_root= (const float*)d_in[14];

    float* out = (float*)d_out;
    float* enc = out + (size_t)NNODES * D_IN;

    float *z2root, *z4;
    f16 *x16, *aggx16, *h116, *h216, *ah216, *z2r16, *aggy16;
    f16 *w1r16, *w1o16, *w216, *w3r16, *w3o16, *w416;
    cudaGetSymbolAddress((void**)&z2root, g_z2root);
    cudaGetSymbolAddress((void**)&z4, g_z4);
    cudaGetSymbolAddress((void**)&x16, g_x16);     cudaGetSymbolAddress((void**)&aggx16, g_aggx16);
    cudaGetSymbolAddress((void**)&h116, g_h116);   cudaGetSymbolAddress((void**)&h216, g_h216);
    cudaGetSymbolAddress((void**)&ah216, g_ah216);
    cudaGetSymbolAddress((void**)&z2r16, g_z2r16); cudaGetSymbolAddress((void**)&aggy16, g_aggy16);
    cudaGetSymbolAddress((void**)&w1r16, g_w1r16); cudaGetSymbolAddress((void**)&w1o16, g_w1o16);
    cudaGetSymbolAddress((void**)&w216, g_w216);
    cudaGetSymbolAddress((void**)&w3r16, g_w3r16); cudaGetSymbolAddress((void**)&w3o16, g_w3o16);
    cudaGetSymbolAddress((void**)&w416, g_w416);

    const int T = 256;
    const int MB = (NNODES + 127) / 128;   // 391
    constexpr int SMEM = 2 * GSTAGE;       // 73728

    cudaFuncSetAttribute(mmagemm<true,  true,  true,  true,  false, false>, cudaFuncAttributeMaxDynamicSharedMemorySize, SMEM);
    cudaFuncSetAttribute(mmagemm<false, false, false, false, false, true >, cudaFuncAttributeMaxDynamicSharedMemorySize, SMEM);
    cudaFuncSetAttribute(mmagemm<false, false, false, false, true,  false>, cudaFuncAttributeMaxDynamicSharedMemorySize, SMEM);

    // ---- setup
    detect_kernel<<<1, 1>>>(ei_raw);
    convert_kernel<<<(2 * NEDGES + T - 1) / T, T>>>(ei_raw, batch_raw);
    zero_all_kernel<<<1024, T>>>();
    split_static_kernel<<<1024, T>>>(W1_rel, W1_root, W2_rel, W2_root,
                                     W3_rel, W3_root, W4_rel, W4_root, x);

    // ---- L1: fp16 agg(x16) then dual-A MMA -> h1 (fp16, relu, bias)
    edge_agg_f16_kernel<64><<<(NEDGES * 8 + T - 1) / T, T>>>(x16, aggx16);
    {
        dim3 grid((D_H + 127) / 128, MB);
        mmagemm<true, true, true, true, false, false><<<grid, T, SMEM>>>(
            nullptr, h116,
            aggx16, x16,
            w1r16, w1o16,
            b1, NNODES, D_IN, D_H, nullptr, nullptr);
    }

    // ---- L2: single-A MMA (K=1000, O=256 cat); rel -> z2r16 fp16, root -> z2root fp32
    {
        dim3 grid(2, MB);
        mmagemm<false, false, false, false, false, true><<<grid, T, SMEM>>>(
            nullptr, z2r16,
            h116, nullptr,
            w216, nullptr,
            nullptr, NNODES, D_H, 256, z2root, nullptr);
    }
    edge_agg_f16_kernel<128><<<(NEDGES * 16 + T - 1) / T, T>>>(z2r16, aggy16);
    combine_pool_kernel<<<(NNODES * 64 + T - 1) / T, T>>>(b2);
    encoded_kernel<<<(NGRAPH * D_ENC + T - 1) / T, T>>>(enc);

    // ---- L3: fp16 agg(h216) then dual-A MMA -> h3 (reuse h1 buffer)
    edge_agg_f16_kernel<128><<<(NEDGES * 16 + T - 1) / T, T>>>(h216, ah216);
    {
        dim3 grid((D_H + 127) / 128, MB);
        mmagemm<true, true, true, true, false, false><<<grid, T, SMEM>>>(
            nullptr, h116,
            ah216, h216,
            w3r16, w3o16,
            b3, NNODES, D_ENC, D_H, nullptr, nullptr);
    }

    // ---- L4: single-A MMA (K=1000, O=128 cat); rel half -> z4, root+b4 -> out
    {
        dim3 grid(1, MB);
        mmagemm<false, false, false, false, true, false><<<grid, T, SMEM>>>(
            z4, nullptr,
            h116, nullptr,
            w416, nullptr,
            nullptr, NNODES, D_H, 128, out, b4);
    }
    edge_agg_kernel<64><<<(NEDGES * 16 + T - 1) / T, T>>>(z4, 64, out, D_IN);
}